// round 1
// baseline (speedup 1.0000x reference)
#include <cuda_runtime.h>
#include <math.h>

// Problem constants (fixed by the dataset instance)
#define NN 20000          // nodes
#define EE 200000         // edges
#define QB 256            // queries
#define NUM_REL 200
#define NUM_TS 365
#define NPAIR (NUM_REL*NUM_TS)   // 73000
#define DIM 128           // 2h

// ---------------- scratch (static device globals; no allocation) ----------------
__device__ __align__(128) float g_x[NN*DIM];        // node state
__device__ __align__(128) float g_Y1[NN*DIM];       // x @ W_fc[0:128]
__device__ __align__(128) float g_Y3[NN*DIM];       // x @ W_fc[256:384]
__device__ __align__(128) float g_RA[NUM_REL*DIM];  // rel_emb @ W_rt[0:64]
__device__ __align__(128) float g_TA[NUM_TS*DIM];   // time_emb @ W_rt[64:128]
__device__ __align__(128) float g_RELT[NPAIR*DIM];  // lrelu(RA+TA+b_rt)
__device__ __align__(128) float g_R2T[NPAIR*DIM];   // RELT @ W_fc[128:256] + b_fc
__device__ int g_deg[NN];
__device__ int g_off[NN+1];
__device__ int g_cursor[NN];
__device__ int g_srcS[EE];
__device__ int g_pairS[EE];
__device__ int g_qmask[NN];

__device__ __forceinline__ float lrelu(float v){ return fmaxf(v,0.f) + 0.2f*fminf(v,0.f); }

// ---------------- generic tiled SGEMM: C = act(A@B + bias) ----------------
// 128x128 block tile, 8x8 per-thread microtile, K chunks of 16, 256 threads.
__global__ __launch_bounds__(256) void sgemm_kernel(
    const float* __restrict__ A, int lda,
    const float* __restrict__ B, int ldb,
    float* __restrict__ C, int ldc,
    int M, int N, int K,
    const float* __restrict__ bias, int act)
{
    __shared__ __align__(16) float As[16][128];   // [k][m]
    __shared__ __align__(16) float Bs[16][128];   // [k][n]
    const int tid = threadIdx.x;
    const int bm = blockIdx.x * 128;
    const int bn = blockIdx.y * 128;
    const int tx = tid & 15, ty = tid >> 4;
    const int a_row = tid >> 2;
    const int a_col = (tid & 3) << 2;
    const int b_row = tid >> 5;
    const int b_col = (tid & 31) << 2;

    float acc[8][8];
    #pragma unroll
    for (int i = 0; i < 8; i++)
        #pragma unroll
        for (int j = 0; j < 8; j++) acc[i][j] = 0.f;

    for (int k0 = 0; k0 < K; k0 += 16) {
        #pragma unroll
        for (int h = 0; h < 2; h++) {
            int r = bm + a_row + h*64;
            float4 v = make_float4(0.f,0.f,0.f,0.f);
            if (r < M) v = *(const float4*)(A + (size_t)r*lda + k0 + a_col);
            As[a_col+0][a_row+h*64] = v.x;
            As[a_col+1][a_row+h*64] = v.y;
            As[a_col+2][a_row+h*64] = v.z;
            As[a_col+3][a_row+h*64] = v.w;
        }
        #pragma unroll
        for (int h = 0; h < 2; h++) {
            int kr = k0 + b_row + h*8;
            int c  = bn + b_col;
            float4 v = make_float4(0.f,0.f,0.f,0.f);
            if (c < N) v = *(const float4*)(B + (size_t)kr*ldb + c);
            *(float4*)&Bs[b_row+h*8][b_col] = v;
        }
        __syncthreads();
        #pragma unroll
        for (int k = 0; k < 16; k++) {
            float4 a0 = *(const float4*)&As[k][ty*4];
            float4 a1 = *(const float4*)&As[k][64 + ty*4];
            float4 b0 = *(const float4*)&Bs[k][tx*4];
            float4 b1 = *(const float4*)&Bs[k][64 + tx*4];
            float av[8] = {a0.x,a0.y,a0.z,a0.w,a1.x,a1.y,a1.z,a1.w};
            float bv[8] = {b0.x,b0.y,b0.z,b0.w,b1.x,b1.y,b1.z,b1.w};
            #pragma unroll
            for (int i = 0; i < 8; i++)
                #pragma unroll
                for (int j = 0; j < 8; j++)
                    acc[i][j] += av[i]*bv[j];
        }
        __syncthreads();
    }
    #pragma unroll
    for (int i = 0; i < 8; i++) {
        int r = bm + ((i < 4) ? ty*4 + i : 64 + ty*4 + (i-4));
        if (r >= M) continue;
        #pragma unroll
        for (int jh = 0; jh < 2; jh++) {
            int c = bn + jh*64 + tx*4;
            if (c >= N) continue;   // N is a multiple of 64 here
            float4 bb = bias ? *(const float4*)(bias + c) : make_float4(0.f,0.f,0.f,0.f);
            float4 o;
            o.x = acc[i][jh*4+0] + bb.x;
            o.y = acc[i][jh*4+1] + bb.y;
            o.z = acc[i][jh*4+2] + bb.z;
            o.w = acc[i][jh*4+3] + bb.w;
            if (act) { o.x=lrelu(o.x); o.y=lrelu(o.y); o.z=lrelu(o.z); o.w=lrelu(o.w); }
            *(float4*)(C + (size_t)r*ldc + c) = o;
        }
    }
}

// ---------------- x[:,64:128] = node_grp_emb[node_ent] ----------------
__global__ void grp_gather_kernel(const float* __restrict__ grp, const int* __restrict__ ent){
    int idx = blockIdx.x*blockDim.x + threadIdx.x;   // NN*16 float4 chunks
    if (idx >= NN*16) return;
    int n = idx >> 4, j = (idx & 15) << 2;
    int e = ent[n];
    *(float4*)&g_x[(size_t)n*DIM + 64 + j] = *(const float4*)&grp[(size_t)e*64 + j];
}

// ---------------- RELT[p] = lrelu(RA[r] + TA[t] + b_rt) ----------------
__global__ void relt_kernel(const float* __restrict__ b_rt){
    int idx = blockIdx.x*blockDim.x + threadIdx.x;   // NPAIR*32 float4 chunks
    if (idx >= NPAIR*32) return;
    int p = idx >> 5, c = (idx & 31) << 2;
    int r = p / NUM_TS, t = p - r*NUM_TS;
    float4 ra = *(const float4*)&g_RA[r*DIM + c];
    float4 ta = *(const float4*)&g_TA[t*DIM + c];
    float4 bb = *(const float4*)(b_rt + c);
    float4 o;
    o.x = lrelu(ra.x + ta.x + bb.x);
    o.y = lrelu(ra.y + ta.y + bb.y);
    o.z = lrelu(ra.z + ta.z + bb.z);
    o.w = lrelu(ra.w + ta.w + bb.w);
    *(float4*)&g_RELT[(size_t)p*DIM + c] = o;
}

// ---------------- CSR build ----------------
__global__ void hist_kernel(const int* __restrict__ dst){
    int e = blockIdx.x*blockDim.x + threadIdx.x;
    if (e < EE) atomicAdd(&g_deg[dst[e]], 1);
}

__global__ void scan_kernel(){
    __shared__ int warp_sums[32];
    __shared__ int s_carry;
    int tid = threadIdx.x;
    int lane = tid & 31, wid = tid >> 5;
    if (tid == 0) s_carry = 0;
    __syncthreads();
    for (int base = 0; base < NN; base += 1024){
        int i = base + tid;
        int v = (i < NN) ? g_deg[i] : 0;
        int x = v;
        #pragma unroll
        for (int d = 1; d < 32; d <<= 1){
            int y = __shfl_up_sync(0xffffffffu, x, d);
            if (lane >= d) x += y;
        }
        if (lane == 31) warp_sums[wid] = x;
        __syncthreads();
        if (tid < 32){
            int w = warp_sums[tid];
            #pragma unroll
            for (int d = 1; d < 32; d <<= 1){
                int y = __shfl_up_sync(0xffffffffu, w, d);
                if (tid >= d) w += y;
            }
            warp_sums[tid] = w;
        }
        __syncthreads();
        int prefix = s_carry + (wid ? warp_sums[wid-1] : 0);
        if (i < NN) g_off[i] = x + prefix - v;   // exclusive
        __syncthreads();
        if (tid == 0) s_carry += warp_sums[31];
        __syncthreads();
    }
    if (threadIdx.x == 0) g_off[NN] = s_carry;
}

__global__ void scatter_kernel(const int* __restrict__ src, const int* __restrict__ dst,
                               const int* __restrict__ rel, const int* __restrict__ ts){
    int e = blockIdx.x*blockDim.x + threadIdx.x;
    if (e >= EE) return;
    int d = dst[e];
    int pos = g_off[d] + atomicAdd(&g_cursor[d], 1);
    g_srcS[pos]  = src[e];
    g_pairS[pos] = rel[e]*NUM_TS + ts[e];
}

// deterministic ordering within each segment (atomic scatter order is not)
__global__ void sortseg_kernel(){
    int n = blockIdx.x*blockDim.x + threadIdx.x;
    if (n >= NN) return;
    int beg = g_off[n], end = g_off[n+1];
    for (int i = beg + 1; i < end; i++){
        int s = g_srcS[i], p = g_pairS[i];
        long long key = ((long long)s << 17) | p;
        int j = i - 1;
        while (j >= beg){
            long long kj = ((long long)g_srcS[j] << 17) | g_pairS[j];
            if (kj <= key) break;
            g_srcS[j+1] = g_srcS[j];
            g_pairS[j+1] = g_pairS[j];
            j--;
        }
        g_srcS[j+1] = s; g_pairS[j+1] = p;
    }
}

__global__ void qmask_kernel(const int* __restrict__ qo){
    int b = threadIdx.x;
    if (b < QB) g_qmask[qo[b]] = 1;
}

// ---------------- fused aggregate: x[n] += mean_e lrelu(Y1[src]+R2T[pair]+Y3[n]) ----------------
__global__ __launch_bounds__(256) void aggregate_kernel(int masked){
    int w = (blockIdx.x*blockDim.x + threadIdx.x) >> 5;
    int lane = threadIdx.x & 31;
    if (w >= NN) return;
    if (masked && g_qmask[w] == 0) return;
    int beg = g_off[w], end = g_off[w+1];
    if (beg == end) return;
    int c = lane << 2;
    float4 y3 = *(const float4*)&g_Y3[(size_t)w*DIM + c];
    float4 acc = make_float4(0.f,0.f,0.f,0.f);
    for (int i = beg; i < end; i++){
        int s = g_srcS[i], p = g_pairS[i];
        float4 a = *(const float4*)&g_Y1[(size_t)s*DIM + c];
        float4 b = *(const float4*)&g_R2T[(size_t)p*DIM + c];
        acc.x += lrelu(a.x + b.x + y3.x);
        acc.y += lrelu(a.y + b.y + y3.y);
        acc.z += lrelu(a.z + b.z + y3.z);
        acc.w += lrelu(a.w + b.w + y3.w);
    }
    float inv = 1.f / (float)(end - beg);
    float4* xp = (float4*)&g_x[(size_t)w*DIM + c];
    float4 xv = *xp;
    xv.x += acc.x*inv; xv.y += acc.y*inv; xv.z += acc.z*inv; xv.w += acc.w*inv;
    *xp = xv;
}

// ---------------- prediction ----------------
__global__ void predict_kernel(const int* __restrict__ qs, const int* __restrict__ qo,
                               const int* __restrict__ qr, const int* __restrict__ qt,
                               const float* __restrict__ b_rt, const float* __restrict__ wp,
                               const float* __restrict__ bp, float* __restrict__ out){
    int w = (blockIdx.x*blockDim.x + threadIdx.x) >> 5;
    int lane = threadIdx.x & 31;
    if (w >= QB) return;
    int s = qs[w], o = qo[w], r = qr[w], t = qt[w];
    int c = lane << 2;
    float4 ra = *(const float4*)&g_RA[r*DIM + c];
    float4 ta = *(const float4*)&g_TA[t*DIM + c];
    float4 bb = *(const float4*)(b_rt + c);
    float q0 = lrelu(ra.x + ta.x + bb.x);
    float q1 = lrelu(ra.y + ta.y + bb.y);
    float q2 = lrelu(ra.z + ta.z + bb.z);
    float q3 = lrelu(ra.w + ta.w + bb.w);
    float4 xs = *(const float4*)&g_x[(size_t)s*DIM + c];
    float4 xo = *(const float4*)&g_x[(size_t)o*DIM + c];
    float4 w1 = *(const float4*)(wp + c);
    float4 w2 = *(const float4*)(wp + 128 + c);
    float4 w3 = *(const float4*)(wp + 256 + c);
    float sum = xs.x*w1.x + xs.y*w1.y + xs.z*w1.z + xs.w*w1.w
              + q0*w2.x + q1*w2.y + q2*w2.z + q3*w2.w
              + xo.x*w3.x + xo.y*w3.y + xo.z*w3.z + xo.w*w3.w;
    #pragma unroll
    for (int d = 16; d; d >>= 1) sum += __shfl_xor_sync(0xffffffffu, sum, d);
    if (lane == 0) out[w] = 1.f / (1.f + expf(-(sum + bp[0])));
}

// ---------------- host ----------------
extern "C" void kernel_launch(void* const* d_in, const int* in_sizes, int n_in,
                              void* d_out, int out_size){
    (void)in_sizes; (void)n_in; (void)out_size;
    const float* x_feat  = (const float*)d_in[0];
    const float* grp     = (const float*)d_in[1];
    const float* rel_emb = (const float*)d_in[2];
    const float* time_e  = (const float*)d_in[3];
    const float* W_node  = (const float*)d_in[4];
    const float* b_node  = (const float*)d_in[5];
    const float* W_rt    = (const float*)d_in[6];
    const float* b_rt    = (const float*)d_in[7];
    const float* W_fc    = (const float*)d_in[8];
    const float* b_fc    = (const float*)d_in[9];
    const float* w_pred  = (const float*)d_in[10];
    const float* b_pred  = (const float*)d_in[11];
    const int* node_ent  = (const int*)d_in[12];
    const int* edge_src  = (const int*)d_in[13];
    const int* edge_dst  = (const int*)d_in[14];
    const int* edge_type = (const int*)d_in[15];
    const int* edge_ts   = (const int*)d_in[16];
    const int* q_s = (const int*)d_in[17];
    const int* q_o = (const int*)d_in[18];
    const int* q_r = (const int*)d_in[19];
    const int* q_t = (const int*)d_in[20];
    float* out = (float*)d_out;

    float *px, *py1, *py3, *pra, *pta, *prelt, *pr2t;
    void  *p_deg, *p_cur, *p_qm;
    cudaGetSymbolAddress((void**)&px,    g_x);
    cudaGetSymbolAddress((void**)&py1,   g_Y1);
    cudaGetSymbolAddress((void**)&py3,   g_Y3);
    cudaGetSymbolAddress((void**)&pra,   g_RA);
    cudaGetSymbolAddress((void**)&pta,   g_TA);
    cudaGetSymbolAddress((void**)&prelt, g_RELT);
    cudaGetSymbolAddress((void**)&pr2t,  g_R2T);
    cudaGetSymbolAddress(&p_deg, g_deg);
    cudaGetSymbolAddress(&p_cur, g_cursor);
    cudaGetSymbolAddress(&p_qm,  g_qmask);

    cudaMemsetAsync(p_deg, 0, NN*sizeof(int));
    cudaMemsetAsync(p_cur, 0, NN*sizeof(int));
    cudaMemsetAsync(p_qm,  0, NN*sizeof(int));

    // node init: x[:,0:64] = lrelu(x_feat @ W_node + b_node); x[:,64:128] = grp_emb gather
    sgemm_kernel<<<dim3((NN+127)/128, 1), 256>>>(x_feat,128, W_node,64, px,DIM, NN,64,128, b_node, 1);
    grp_gather_kernel<<<(NN*16 + 255)/256, 256>>>(grp, node_ent);

    // relation/time tables
    sgemm_kernel<<<dim3((NUM_REL+127)/128, 1), 256>>>(rel_emb,64, W_rt,128,        pra,DIM, NUM_REL,128,64, (const float*)0, 0);
    sgemm_kernel<<<dim3((NUM_TS +127)/128, 1), 256>>>(time_e, 64, W_rt + 64*128,128, pta,DIM, NUM_TS,128,64, (const float*)0, 0);
    relt_kernel<<<(NPAIR*32 + 255)/256, 256>>>(b_rt);
    // R2T = RELT @ W_fc[128:256] + b_fc  (b_fc folded here once)
    sgemm_kernel<<<dim3((NPAIR+127)/128, 1), 256>>>(prelt,DIM, W_fc + 128*128,128, pr2t,DIM, NPAIR,128,128, b_fc, 0);

    // CSR by dst (deterministic after segment sort)
    hist_kernel<<<(EE+255)/256, 256>>>(edge_dst);
    scan_kernel<<<1, 1024>>>();
    scatter_kernel<<<(EE+255)/256, 256>>>(edge_src, edge_dst, edge_type, edge_ts);
    sortseg_kernel<<<(NN+255)/256, 256>>>();
    qmask_kernel<<<1, 256>>>(q_o);

    // 2 full hops + 1 masked final hop (num_hops = 2 in this instance)
    for (int hop = 0; hop < 3; hop++){
        sgemm_kernel<<<dim3((NN+127)/128, 1), 256>>>(px,DIM, W_fc,          128, py1,DIM, NN,128,128, (const float*)0, 0);
        sgemm_kernel<<<dim3((NN+127)/128, 1), 256>>>(px,DIM, W_fc + 256*128,128, py3,DIM, NN,128,128, (const float*)0, 0);
        aggregate_kernel<<<(NN*32 + 255)/256, 256>>>(hop == 2 ? 1 : 0);
    }

    predict_kernel<<<(QB*32 + 255)/256, 256>>>(q_s, q_o, q_r, q_t, b_rt, w_pred, b_pred, out);
}

// round 3
// speedup vs baseline: 1.4810x; 1.4810x over previous
#include <cuda_runtime.h>
#include <cuda_bf16.h>
#include <math.h>
#include <stdint.h>

// Problem constants (fixed by the dataset instance)
#define NN 20000          // nodes
#define EE 200000         // edges
#define QB 256            // queries
#define NUM_REL 200
#define NUM_TS 365
#define NPAIR (NUM_REL*NUM_TS)   // 73000
#define DIM 128           // 2h

// ---------------- scratch (static device globals; no allocation) ----------------
__device__ __align__(128) float g_x[NN*DIM];        // node state
__device__ __align__(128) float g_Y1[NN*DIM];       // x @ W_fc[0:128]
__device__ __align__(128) float g_Y3[NN*DIM];       // x @ W_fc[256:384]
__device__ __align__(128) float g_RA[NUM_REL*DIM];  // rel_emb @ W_rt[0:64]
__device__ __align__(128) float g_TA[NUM_TS*DIM];   // time_emb @ W_rt[64:128]
__device__ __align__(128) float g_RELT[NPAIR*DIM];  // lrelu(RA+TA+b_rt)
__device__ __align__(128) float g_R2T[NPAIR*DIM];   // RELT @ W_fc[128:256] + b_fc

// transposed weight splits, each [128 n-rows][128 k-cols] bf16 (zero padded):
// 0:W1t0 1:W1t1 2:W2t0 3:W2t1 4:W3t0 5:W3t1 6:Wnt0 7:Wnt1
__device__ __align__(128) __nv_bfloat16 g_WT[8*16384];

__device__ int g_deg[NN];
__device__ int g_off[NN+1];
__device__ int g_cursor[NN];
__device__ int g_srcS[EE];
__device__ int g_pairS[EE];
__device__ int g_qmask[NN];

__device__ __forceinline__ float lrelu(float v){ return fmaxf(v,0.f) + 0.2f*fminf(v,0.f); }

// ============================================================================
// HMMA bf16x3 GEMM: C[M, n_out] = A_fp32[M,128] @ ((B0+B1)[n][k])^T
// A split in-kernel into bf16 hi/lo; TMEM-free warp-level mma.sync path
// (portable PTX — this bench's ptxas target is sm_103 without the 'a' features).
// One CTA per 128-row tile; 8 warps in 4(m) x 2(n); warp tile 32x64.
// ============================================================================
#define GPAD 136   // bf16 elements per smem row (128 + 8 pad -> conflict-free)
#define MMA_SMEM_BYTES (4*128*GPAD*2)   // A0,A1,B0,B1 tiles = 139264 B

__device__ __forceinline__ void mma16816(float* c, const uint32_t* a, const uint32_t* b){
    asm volatile(
        "mma.sync.aligned.m16n8k16.row.col.f32.bf16.bf16.f32 "
        "{%0,%1,%2,%3}, {%4,%5,%6,%7}, {%8,%9}, {%0,%1,%2,%3};"
        : "+f"(c[0]), "+f"(c[1]), "+f"(c[2]), "+f"(c[3])
        : "r"(a[0]), "r"(a[1]), "r"(a[2]), "r"(a[3]), "r"(b[0]), "r"(b[1]));
}

__global__ __launch_bounds__(256, 1) void hmma_gemm_kernel(
    const float* __restrict__ A,
    const __nv_bfloat16* __restrict__ Bt0, const __nv_bfloat16* __restrict__ Bt1,
    float* __restrict__ C, int ldc, int M, int n_out,
    const float* __restrict__ bias, int act)
{
    extern __shared__ __align__(16) char smem[];
    __nv_bfloat16* sA0 = (__nv_bfloat16*)smem;
    __nv_bfloat16* sA1 = sA0 + 128*GPAD;
    __nv_bfloat16* sB0 = sA1 + 128*GPAD;
    __nv_bfloat16* sB1 = sB0 + 128*GPAD;

    const int tid = threadIdx.x;
    const int wid = tid >> 5, lane = tid & 31;
    const int bm = blockIdx.x * 128;

    // ---- fill A (fp32 -> bf16 hi/lo split) ----
    #pragma unroll
    for (int t = 0; t < 16; t++) {
        int idx = tid + t*256;               // 4096 float4 slots
        int row = idx >> 5, c4 = (idx & 31) << 2;
        float4 v = make_float4(0.f,0.f,0.f,0.f);
        if (bm + row < M) v = *(const float4*)(A + (size_t)(bm + row)*128 + c4);
        __nv_bfloat16 h0=__float2bfloat16(v.x), h1=__float2bfloat16(v.y),
                      h2=__float2bfloat16(v.z), h3=__float2bfloat16(v.w);
        __nv_bfloat16* d0 = sA0 + row*GPAD + c4;
        __nv_bfloat16* d1 = sA1 + row*GPAD + c4;
        *(__nv_bfloat162*)(d0+0) = __halves2bfloat162(h0,h1);
        *(__nv_bfloat162*)(d0+2) = __halves2bfloat162(h2,h3);
        *(__nv_bfloat162*)(d1+0) = __halves2bfloat162(
            __float2bfloat16(v.x-__bfloat162float(h0)), __float2bfloat16(v.y-__bfloat162float(h1)));
        *(__nv_bfloat162*)(d1+2) = __halves2bfloat162(
            __float2bfloat16(v.z-__bfloat162float(h2)), __float2bfloat16(v.w-__bfloat162float(h3)));
    }
    // ---- fill B tiles (already bf16, [n][k] row-major) ----
    #pragma unroll
    for (int t = 0; t < 8; t++) {
        int idx = tid + t*256;               // 2048 float4 (8-bf16) slots
        int row = idx >> 4, c8 = (idx & 15) << 3;
        *(float4*)(sB0 + row*GPAD + c8) = *(const float4*)(Bt0 + (size_t)row*128 + c8);
        *(float4*)(sB1 + row*GPAD + c8) = *(const float4*)(Bt1 + (size_t)row*128 + c8);
    }
    __syncthreads();

    const int warp_m = wid & 3;              // 0..3 -> m offset 32*warp_m
    const int warp_n = wid >> 2;             // 0..1 -> n offset 64*warp_n
    const int gid = lane >> 2;               // 0..7
    const int q2  = (lane & 3) << 1;         // 0,2,4,6

    float acc[2][8][4];
    #pragma unroll
    for (int i = 0; i < 2; i++)
        #pragma unroll
        for (int j = 0; j < 8; j++)
            #pragma unroll
            for (int q = 0; q < 4; q++) acc[i][j][q] = 0.f;

    #pragma unroll 1
    for (int p = 0; p < 3; p++) {
        const __nv_bfloat16* Ab = (p == 2) ? sA1 : sA0;
        const __nv_bfloat16* Bb = (p == 1) ? sB1 : sB0;
        #pragma unroll 1
        for (int ks = 0; ks < 8; ks++) {
            const int k0 = ks * 16;
            uint32_t a[2][4];
            #pragma unroll
            for (int i = 0; i < 2; i++) {
                int m0 = warp_m*32 + i*16 + gid;
                a[i][0] = *(const uint32_t*)(Ab + m0*GPAD     + k0 + q2);
                a[i][1] = *(const uint32_t*)(Ab + (m0+8)*GPAD + k0 + q2);
                a[i][2] = *(const uint32_t*)(Ab + m0*GPAD     + k0 + q2 + 8);
                a[i][3] = *(const uint32_t*)(Ab + (m0+8)*GPAD + k0 + q2 + 8);
            }
            uint32_t b[8][2];
            #pragma unroll
            for (int j = 0; j < 8; j++) {
                int n0 = warp_n*64 + j*8 + gid;
                b[j][0] = *(const uint32_t*)(Bb + n0*GPAD + k0 + q2);
                b[j][1] = *(const uint32_t*)(Bb + n0*GPAD + k0 + q2 + 8);
            }
            #pragma unroll
            for (int i = 0; i < 2; i++)
                #pragma unroll
                for (int j = 0; j < 8; j++)
                    mma16816(acc[i][j], a[i], b[j]);
        }
    }

    // ---- epilogue ----
    #pragma unroll
    for (int i = 0; i < 2; i++) {
        int row0 = bm + warp_m*32 + i*16 + gid;
        #pragma unroll
        for (int j = 0; j < 8; j++) {
            int col = warp_n*64 + j*8 + q2;
            if (col >= n_out) continue;
            float bx = 0.f, by = 0.f;
            if (bias) { float2 bb = *(const float2*)(bias + col); bx = bb.x; by = bb.y; }
            if (row0 < M) {
                float2 o = make_float2(acc[i][j][0] + bx, acc[i][j][1] + by);
                if (act) { o.x = lrelu(o.x); o.y = lrelu(o.y); }
                *(float2*)(C + (size_t)row0*ldc + col) = o;
            }
            if (row0 + 8 < M) {
                float2 o = make_float2(acc[i][j][2] + bx, acc[i][j][3] + by);
                if (act) { o.x = lrelu(o.x); o.y = lrelu(o.y); }
                *(float2*)(C + (size_t)(row0+8)*ldc + col) = o;
            }
        }
    }
}

// ---------------- small GEMM C[M,128] = A[M,64] @ B[64,128] (latency path) ----------------
__global__ void small_mm_kernel(const float* __restrict__ A, const float* __restrict__ B,
                                float* __restrict__ C, int M){
    int idx = blockIdx.x*blockDim.x + threadIdx.x;
    if (idx >= M*128) return;
    int row = idx >> 7, col = idx & 127;
    const float* a = A + row*64;
    float s = 0.f;
    #pragma unroll
    for (int k = 0; k < 64; k++) s = fmaf(__ldg(a + k), __ldg(B + k*128 + col), s);
    C[idx] = s;
}

// weight transpose+split: Bt[n][k] = W[k*ld + n] (n >= nout -> 0)
__global__ void wsplit_kernel(const float* __restrict__ W, int ld, int nout,
                              __nv_bfloat16* __restrict__ t0, __nv_bfloat16* __restrict__ t1){
    int idx = blockIdx.x*blockDim.x + threadIdx.x;
    if (idx >= 16384) return;
    int n = idx >> 7, k = idx & 127;
    float v = (n < nout) ? W[k*ld + n] : 0.f;
    __nv_bfloat16 h = __float2bfloat16(v);
    t0[idx] = h;
    t1[idx] = __float2bfloat16(v - __bfloat162float(h));
}

// ---------------- x[:,64:128] = node_grp_emb[node_ent] ----------------
__global__ void grp_gather_kernel(const float* __restrict__ grp, const int* __restrict__ ent){
    int idx = blockIdx.x*blockDim.x + threadIdx.x;
    if (idx >= NN*16) return;
    int n = idx >> 4, j = (idx & 15) << 2;
    int e = ent[n];
    *(float4*)&g_x[(size_t)n*DIM + 64 + j] = *(const float4*)&grp[(size_t)e*64 + j];
}

// ---------------- RELT[p] = lrelu(RA[r] + TA[t] + b_rt) ----------------
__global__ void relt_kernel(const float* __restrict__ b_rt){
    int idx = blockIdx.x*blockDim.x + threadIdx.x;
    if (idx >= NPAIR*32) return;
    int p = idx >> 5, c = (idx & 31) << 2;
    int r = p / NUM_TS, t = p - r*NUM_TS;
    float4 ra = *(const float4*)&g_RA[r*DIM + c];
    float4 ta = *(const float4*)&g_TA[t*DIM + c];
    float4 bb = *(const float4*)(b_rt + c);
    float4 o;
    o.x = lrelu(ra.x + ta.x + bb.x);
    o.y = lrelu(ra.y + ta.y + bb.y);
    o.z = lrelu(ra.z + ta.z + bb.z);
    o.w = lrelu(ra.w + ta.w + bb.w);
    *(float4*)&g_RELT[(size_t)p*DIM + c] = o;
}

// ---------------- CSR build ----------------
__global__ void hist_kernel(const int* __restrict__ dst){
    int e = blockIdx.x*blockDim.x + threadIdx.x;
    if (e < EE) atomicAdd(&g_deg[dst[e]], 1);
}

__global__ void scan_kernel(){
    __shared__ int warp_sums[32];
    __shared__ int s_carry;
    int tid = threadIdx.x;
    int lane = tid & 31, wid = tid >> 5;
    if (tid == 0) s_carry = 0;
    __syncthreads();
    for (int base = 0; base < NN; base += 1024){
        int i = base + tid;
        int v = (i < NN) ? g_deg[i] : 0;
        int x = v;
        #pragma unroll
        for (int d = 1; d < 32; d <<= 1){
            int y = __shfl_up_sync(0xffffffffu, x, d);
            if (lane >= d) x += y;
        }
        if (lane == 31) warp_sums[wid] = x;
        __syncthreads();
        if (tid < 32){
            int w = warp_sums[tid];
            #pragma unroll
            for (int d = 1; d < 32; d <<= 1){
                int y = __shfl_up_sync(0xffffffffu, w, d);
                if (tid >= d) w += y;
            }
            warp_sums[tid] = w;
        }
        __syncthreads();
        int prefix = s_carry + (wid ? warp_sums[wid-1] : 0);
        if (i < NN) g_off[i] = x + prefix - v;   // exclusive
        __syncthreads();
        if (tid == 0) s_carry += warp_sums[31];
        __syncthreads();
    }
    if (threadIdx.x == 0) g_off[NN] = s_carry;
}

__global__ void scatter_kernel(const int* __restrict__ src, const int* __restrict__ dst,
                               const int* __restrict__ rel, const int* __restrict__ ts){
    int e = blockIdx.x*blockDim.x + threadIdx.x;
    if (e >= EE) return;
    int d = dst[e];
    int pos = g_off[d] + atomicAdd(&g_cursor[d], 1);
    g_srcS[pos]  = src[e];
    g_pairS[pos] = rel[e]*NUM_TS + ts[e];
}

// deterministic ordering within each segment
__global__ void sortseg_kernel(){
    int n = blockIdx.x*blockDim.x + threadIdx.x;
    if (n >= NN) return;
    int beg = g_off[n], end = g_off[n+1];
    for (int i = beg + 1; i < end; i++){
        int s = g_srcS[i], p = g_pairS[i];
        long long key = ((long long)s << 17) | p;
        int j = i - 1;
        while (j >= beg){
            long long kj = ((long long)g_srcS[j] << 17) | g_pairS[j];
            if (kj <= key) break;
            g_srcS[j+1] = g_srcS[j];
            g_pairS[j+1] = g_pairS[j];
            j--;
        }
        g_srcS[j+1] = s; g_pairS[j+1] = p;
    }
}

__global__ void qmask_kernel(const int* __restrict__ qo){
    int b = threadIdx.x;
    if (b < QB) g_qmask[qo[b]] = 1;
}

// ---------------- fused aggregate: x[n] += mean_e lrelu(Y1[src]+R2T[pair]+Y3[n]) ----------------
__global__ __launch_bounds__(256) void aggregate_kernel(int masked){
    int w = (blockIdx.x*blockDim.x + threadIdx.x) >> 5;
    int lane = threadIdx.x & 31;
    if (w >= NN) return;
    if (masked && g_qmask[w] == 0) return;
    int beg = g_off[w], end = g_off[w+1];
    if (beg == end) return;
    int c = lane << 2;
    float4 y3 = *(const float4*)&g_Y3[(size_t)w*DIM + c];
    float4 acc = make_float4(0.f,0.f,0.f,0.f);
    for (int i = beg; i < end; i++){
        int s = g_srcS[i], p = g_pairS[i];
        float4 a = *(const float4*)&g_Y1[(size_t)s*DIM + c];
        float4 b = *(const float4*)&g_R2T[(size_t)p*DIM + c];
        acc.x += lrelu(a.x + b.x + y3.x);
        acc.y += lrelu(a.y + b.y + y3.y);
        acc.z += lrelu(a.z + b.z + y3.z);
        acc.w += lrelu(a.w + b.w + y3.w);
    }
    float inv = 1.f / (float)(end - beg);
    float4* xp = (float4*)&g_x[(size_t)w*DIM + c];
    float4 xv = *xp;
    xv.x += acc.x*inv; xv.y += acc.y*inv; xv.z += acc.z*inv; xv.w += acc.w*inv;
    *xp = xv;
}

// ---------------- prediction ----------------
__global__ void predict_kernel(const int* __restrict__ qs, const int* __restrict__ qo,
                               const int* __restrict__ qr, const int* __restrict__ qt,
                               const float* __restrict__ b_rt, const float* __restrict__ wp,
                               const float* __restrict__ bp, float* __restrict__ out){
    int w = (blockIdx.x*blockDim.x + threadIdx.x) >> 5;
    int lane = threadIdx.x & 31;
    if (w >= QB) return;
    int s = qs[w], o = qo[w], r = qr[w], t = qt[w];
    int c = lane << 2;
    float4 ra = *(const float4*)&g_RA[r*DIM + c];
    float4 ta = *(const float4*)&g_TA[t*DIM + c];
    float4 bb = *(const float4*)(b_rt + c);
    float q0 = lrelu(ra.x + ta.x + bb.x);
    float q1 = lrelu(ra.y + ta.y + bb.y);
    float q2 = lrelu(ra.z + ta.z + bb.z);
    float q3 = lrelu(ra.w + ta.w + bb.w);
    float4 xs = *(const float4*)&g_x[(size_t)s*DIM + c];
    float4 xo = *(const float4*)&g_x[(size_t)o*DIM + c];
    float4 w1 = *(const float4*)(wp + c);
    float4 w2 = *(const float4*)(wp + 128 + c);
    float4 w3 = *(const float4*)(wp + 256 + c);
    float sum = xs.x*w1.x + xs.y*w1.y + xs.z*w1.z + xs.w*w1.w
              + q0*w2.x + q1*w2.y + q2*w2.z + q3*w2.w
              + xo.x*w3.x + xo.y*w3.y + xo.z*w3.z + xo.w*w3.w;
    #pragma unroll
    for (int d = 16; d; d >>= 1) sum += __shfl_xor_sync(0xffffffffu, sum, d);
    if (lane == 0) out[w] = 1.f / (1.f + expf(-(sum + bp[0])));
}

// ---------------- host ----------------
extern "C" void kernel_launch(void* const* d_in, const int* in_sizes, int n_in,
                              void* d_out, int out_size){
    (void)in_sizes; (void)n_in; (void)out_size;
    const float* x_feat  = (const float*)d_in[0];
    const float* grp     = (const float*)d_in[1];
    const float* rel_emb = (const float*)d_in[2];
    const float* time_e  = (const float*)d_in[3];
    const float* W_node  = (const float*)d_in[4];
    const float* b_node  = (const float*)d_in[5];
    const float* W_rt    = (const float*)d_in[6];
    const float* b_rt    = (const float*)d_in[7];
    const float* W_fc    = (const float*)d_in[8];
    const float* b_fc    = (const float*)d_in[9];
    const float* w_pred  = (const float*)d_in[10];
    const float* b_pred  = (const float*)d_in[11];
    const int* node_ent  = (const int*)d_in[12];
    const int* edge_src  = (const int*)d_in[13];
    const int* edge_dst  = (const int*)d_in[14];
    const int* edge_type = (const int*)d_in[15];
    const int* edge_ts   = (const int*)d_in[16];
    const int* q_s = (const int*)d_in[17];
    const int* q_o = (const int*)d_in[18];
    const int* q_r = (const int*)d_in[19];
    const int* q_t = (const int*)d_in[20];
    float* out = (float*)d_out;

    float *px, *py1, *py3, *pra, *pta, *prelt, *pr2t;
    __nv_bfloat16 *pWT;
    void *p_deg, *p_cur, *p_qm;
    cudaGetSymbolAddress((void**)&px,    g_x);
    cudaGetSymbolAddress((void**)&py1,   g_Y1);
    cudaGetSymbolAddress((void**)&py3,   g_Y3);
    cudaGetSymbolAddress((void**)&pra,   g_RA);
    cudaGetSymbolAddress((void**)&pta,   g_TA);
    cudaGetSymbolAddress((void**)&prelt, g_RELT);
    cudaGetSymbolAddress((void**)&pr2t,  g_R2T);
    cudaGetSymbolAddress((void**)&pWT,   g_WT);
    cudaGetSymbolAddress(&p_deg, g_deg);
    cudaGetSymbolAddress(&p_cur, g_cursor);
    cudaGetSymbolAddress(&p_qm,  g_qmask);

    cudaFuncSetAttribute(hmma_gemm_kernel, cudaFuncAttributeMaxDynamicSharedMemorySize, MMA_SMEM_BYTES);

    cudaMemsetAsync(p_deg, 0, NN*sizeof(int));
    cudaMemsetAsync(p_cur, 0, NN*sizeof(int));
    cudaMemsetAsync(p_qm,  0, NN*sizeof(int));

    __nv_bfloat16* W1t0 = pWT + 0*16384;  __nv_bfloat16* W1t1 = pWT + 1*16384;
    __nv_bfloat16* W2t0 = pWT + 2*16384;  __nv_bfloat16* W2t1 = pWT + 3*16384;
    __nv_bfloat16* W3t0 = pWT + 4*16384;  __nv_bfloat16* W3t1 = pWT + 5*16384;
    __nv_bfloat16* Wnt0 = pWT + 6*16384;  __nv_bfloat16* Wnt1 = pWT + 7*16384;

    // weight transposes + splits (tiny)
    wsplit_kernel<<<64, 256>>>(W_fc,           128, 128, W1t0, W1t1);
    wsplit_kernel<<<64, 256>>>(W_fc + 128*128, 128, 128, W2t0, W2t1);
    wsplit_kernel<<<64, 256>>>(W_fc + 256*128, 128, 128, W3t0, W3t1);
    wsplit_kernel<<<64, 256>>>(W_node,          64,  64, Wnt0, Wnt1);

    // node init: x[:,0:64] = lrelu(x_feat @ W_node + b_node)  (tensor cores)
    hmma_gemm_kernel<<<(NN+127)/128, 256, MMA_SMEM_BYTES>>>(x_feat, Wnt0, Wnt1,
                                                            px, DIM, NN, 64, b_node, 1);
    grp_gather_kernel<<<(NN*16 + 255)/256, 256>>>(grp, node_ent);

    // relation/time tables
    small_mm_kernel<<<(NUM_REL*128 + 255)/256, 256>>>(rel_emb, W_rt,          pra, NUM_REL);
    small_mm_kernel<<<(NUM_TS *128 + 255)/256, 256>>>(time_e,  W_rt + 64*128, pta, NUM_TS);
    relt_kernel<<<(NPAIR*32 + 255)/256, 256>>>(b_rt);
    // R2T = RELT @ W_fc[128:256] + b_fc
    hmma_gemm_kernel<<<(NPAIR+127)/128, 256, MMA_SMEM_BYTES>>>(prelt, W2t0, W2t1,
                                                               pr2t, DIM, NPAIR, 128, b_fc, 0);

    // CSR by dst (deterministic after segment sort)
    hist_kernel<<<(EE+255)/256, 256>>>(edge_dst);
    scan_kernel<<<1, 1024>>>();
    scatter_kernel<<<(EE+255)/256, 256>>>(edge_src, edge_dst, edge_type, edge_ts);
    sortseg_kernel<<<(NN+255)/256, 256>>>();
    qmask_kernel<<<1, 256>>>(q_o);

    // 2 full hops + 1 masked final hop
    for (int hop = 0; hop < 3; hop++){
        hmma_gemm_kernel<<<(NN+127)/128, 256, MMA_SMEM_BYTES>>>(px, W1t0, W1t1,
                                                                py1, DIM, NN, 128, (const float*)0, 0);
        hmma_gemm_kernel<<<(NN+127)/128, 256, MMA_SMEM_BYTES>>>(px, W3t0, W3t1,
                                                                py3, DIM, NN, 128, (const float*)0, 0);
        aggregate_kernel<<<(NN*32 + 255)/256, 256>>>(hop == 2 ? 1 : 0);
    }

    predict_kernel<<<(QB*32 + 255)/256, 256>>>(q_s, q_o, q_r, q_t, b_rt, w_pred, b_pred, out);
}

// round 8
// speedup vs baseline: 1.7254x; 1.1650x over previous
#include <cuda_runtime.h>
#include <cuda_bf16.h>
#include <math.h>
#include <stdint.h>

// Problem constants (fixed by the dataset instance)
#define NN 20000          // nodes
#define EE 200000         // edges
#define QB 256            // queries
#define NUM_REL 200
#define NUM_TS 365
#define NPAIR (NUM_REL*NUM_TS)   // 73000
#define DIM 128           // 2h
#define NTILE ((NN+127)/128)     // 157 row tiles

// ---------------- scratch (static device globals; no allocation) ----------------
__device__ __align__(128) float g_x[NN*DIM];        // node state
__device__ __align__(128) float g_Y1[NN*DIM];       // x @ W_fc[0:128]
__device__ __align__(128) float g_Y3[NN*DIM];       // x @ W_fc[256:384]
__device__ __align__(128) float g_RA[NUM_REL*DIM];  // rel_emb @ W_rt[0:64]
__device__ __align__(128) float g_TA[NUM_TS*DIM];   // time_emb @ W_rt[64:128]
__device__ __align__(128) float g_R2T[NPAIR*DIM];   // lrelu(RA+TA+b_rt) @ W_fc[128:256] + b_fc

// transposed weight splits, each [128 n-rows][128 k-cols] bf16 (zero padded):
// 0:W1t0 1:W1t1 2:W2t0 3:W2t1 4:W3t0 5:W3t1 6:Wnt0 7:Wnt1
__device__ __align__(128) __nv_bfloat16 g_WT[8*16384];

// contiguous int scratch: [deg NN][cursor NN][qmask NN][tileq NTILE]
__device__ int g_iscr[3*NN + NTILE];
#define G_DEG (g_iscr)
#define G_CUR (g_iscr + NN)
#define G_QM  (g_iscr + 2*NN)
#define G_TQ  (g_iscr + 3*NN)

__device__ int g_off[NN+1];
__device__ int g_srcS[EE];
__device__ int g_pairS[EE];

__device__ __forceinline__ float lrelu(float v){ return fmaxf(v,0.f) + 0.2f*fminf(v,0.f); }

// ============================================================================
// HMMA bf16x3 GEMM: C[M, n_out] = A_fp32[M,128] @ ((B0+B1)[n][k])^T
// A split in-kernel into bf16 hi/lo (or generated on the fly for RELT mode).
// gridDim.y selects (B,C,bias) pair -> one launch does Y1 and Y3.
// blockIdx.y==1 + tflags -> per-tile early exit (final-hop masked Y3).
// One CTA per 128-row tile; 8 warps in 4(m) x 2(n); warp tile 32x64.
// ============================================================================
#define GPAD 136   // bf16 elements per smem row (128 + 8 pad -> conflict-free)
#define MMA_SMEM_BYTES (4*128*GPAD*2)   // A0,A1,B0,B1 tiles = 139264 B

__device__ __forceinline__ void mma16816(float* c, const uint32_t* a, const uint32_t* b){
    asm volatile(
        "mma.sync.aligned.m16n8k16.row.col.f32.bf16.bf16.f32 "
        "{%0,%1,%2,%3}, {%4,%5,%6,%7}, {%8,%9}, {%0,%1,%2,%3};"
        : "+f"(c[0]), "+f"(c[1]), "+f"(c[2]), "+f"(c[3])
        : "r"(a[0]), "r"(a[1]), "r"(a[2]), "r"(a[3]), "r"(b[0]), "r"(b[1]));
}

__device__ __forceinline__ void split_store(float4 v, __nv_bfloat16* d0, __nv_bfloat16* d1){
    __nv_bfloat16 h0=__float2bfloat16(v.x), h1=__float2bfloat16(v.y),
                  h2=__float2bfloat16(v.z), h3=__float2bfloat16(v.w);
    *(__nv_bfloat162*)(d0+0) = __halves2bfloat162(h0,h1);
    *(__nv_bfloat162*)(d0+2) = __halves2bfloat162(h2,h3);
    *(__nv_bfloat162*)(d1+0) = __halves2bfloat162(
        __float2bfloat16(v.x-__bfloat162float(h0)), __float2bfloat16(v.y-__bfloat162float(h1)));
    *(__nv_bfloat162*)(d1+2) = __halves2bfloat162(
        __float2bfloat16(v.z-__bfloat162float(h2)), __float2bfloat16(v.w-__bfloat162float(h3)));
}

__global__ __launch_bounds__(256, 1) void hmma_gemm_kernel(
    const float* __restrict__ A, int amode, const float* __restrict__ b_rt,
    const __nv_bfloat16* __restrict__ B0a, const __nv_bfloat16* __restrict__ B1a,
    float* __restrict__ Ca, const float* __restrict__ biasA,
    const __nv_bfloat16* __restrict__ B0b, const __nv_bfloat16* __restrict__ B1b,
    float* __restrict__ Cb, const float* __restrict__ biasB,
    int ldc, int M, int n_out, int act,
    const float* __restrict__ grp, const int* __restrict__ ent,
    const int* __restrict__ tflags)
{
    const int which = blockIdx.y;
    if (tflags && which == 1 && tflags[blockIdx.x] == 0) return;
    const __nv_bfloat16* Bt0 = which ? B0b : B0a;
    const __nv_bfloat16* Bt1 = which ? B1b : B1a;
    float* C = which ? Cb : Ca;
    const float* bias = which ? biasB : biasA;

    extern __shared__ __align__(16) char smem[];
    __nv_bfloat16* sA0 = (__nv_bfloat16*)smem;
    __nv_bfloat16* sA1 = sA0 + 128*GPAD;
    __nv_bfloat16* sB0 = sA1 + 128*GPAD;
    __nv_bfloat16* sB1 = sB0 + 128*GPAD;

    const int tid = threadIdx.x;
    const int wid = tid >> 5, lane = tid & 31;
    const int bm = blockIdx.x * 128;

    // ---- fill A (fp32 -> bf16 hi/lo split); amode 1 = RELT rows on the fly ----
    #pragma unroll
    for (int t = 0; t < 16; t++) {
        int idx = tid + t*256;               // 4096 float4 slots
        int row = idx >> 5, c4 = (idx & 31) << 2;
        float4 v = make_float4(0.f,0.f,0.f,0.f);
        int gr = bm + row;
        if (gr < M) {
            if (amode == 0) {
                v = *(const float4*)(A + (size_t)gr*128 + c4);
            } else {
                int r_ = gr / NUM_TS, t_ = gr - r_*NUM_TS;
                float4 ra = *(const float4*)&g_RA[r_*DIM + c4];
                float4 ta = *(const float4*)&g_TA[t_*DIM + c4];
                float4 bb = *(const float4*)(b_rt + c4);
                v.x = lrelu(ra.x + ta.x + bb.x);
                v.y = lrelu(ra.y + ta.y + bb.y);
                v.z = lrelu(ra.z + ta.z + bb.z);
                v.w = lrelu(ra.w + ta.w + bb.w);
            }
        }
        split_store(v, sA0 + row*GPAD + c4, sA1 + row*GPAD + c4);
    }
    // ---- fill B tiles (already bf16, [n][k] row-major) ----
    #pragma unroll
    for (int t = 0; t < 8; t++) {
        int idx = tid + t*256;               // 2048 float4 (8-bf16) slots
        int row = idx >> 4, c8 = (idx & 15) << 3;
        *(float4*)(sB0 + row*GPAD + c8) = *(const float4*)(Bt0 + (size_t)row*128 + c8);
        *(float4*)(sB1 + row*GPAD + c8) = *(const float4*)(Bt1 + (size_t)row*128 + c8);
    }
    // ---- fused grp gather (node-init only): x[:,64:128] = grp[ent] ----
    if (ent) {
        #pragma unroll
        for (int t = 0; t < 8; t++) {
            int idx = tid + t*256;           // 2048 float4
            int row = idx >> 4, c4 = (idx & 15) << 2;
            int gr = bm + row;
            if (gr < M)
                *(float4*)(Ca + (size_t)gr*ldc + 64 + c4) =
                    *(const float4*)(grp + (size_t)ent[gr]*64 + c4);
        }
    }
    __syncthreads();

    const int warp_m = wid & 3;              // 0..3 -> m offset 32*warp_m
    const int warp_n = wid >> 2;             // 0..1 -> n offset 64*warp_n
    const int gid = lane >> 2;               // 0..7
    const int q2  = (lane & 3) << 1;         // 0,2,4,6

    float acc[2][8][4];
    #pragma unroll
    for (int i = 0; i < 2; i++)
        #pragma unroll
        for (int j = 0; j < 8; j++)
            #pragma unroll
            for (int q = 0; q < 4; q++) acc[i][j][q] = 0.f;

    #pragma unroll 1
    for (int p = 0; p < 3; p++) {
        const __nv_bfloat16* Ab = (p == 2) ? sA1 : sA0;
        const __nv_bfloat16* Bb = (p == 1) ? sB1 : sB0;
        #pragma unroll 1
        for (int ks = 0; ks < 8; ks++) {
            const int k0 = ks * 16;
            uint32_t a[2][4];
            #pragma unroll
            for (int i = 0; i < 2; i++) {
                int m0 = warp_m*32 + i*16 + gid;
                a[i][0] = *(const uint32_t*)(Ab + m0*GPAD     + k0 + q2);
                a[i][1] = *(const uint32_t*)(Ab + (m0+8)*GPAD + k0 + q2);
                a[i][2] = *(const uint32_t*)(Ab + m0*GPAD     + k0 + q2 + 8);
                a[i][3] = *(const uint32_t*)(Ab + (m0+8)*GPAD + k0 + q2 + 8);
            }
            uint32_t b[8][2];
            #pragma unroll
            for (int j = 0; j < 8; j++) {
                int n0 = warp_n*64 + j*8 + gid;
                b[j][0] = *(const uint32_t*)(Bb + n0*GPAD + k0 + q2);
                b[j][1] = *(const uint32_t*)(Bb + n0*GPAD + k0 + q2 + 8);
            }
            #pragma unroll
            for (int i = 0; i < 2; i++)
                #pragma unroll
                for (int j = 0; j < 8; j++)
                    mma16816(acc[i][j], a[i], b[j]);
        }
    }

    // ---- epilogue ----
    #pragma unroll
    for (int i = 0; i < 2; i++) {
        int row0 = bm + warp_m*32 + i*16 + gid;
        #pragma unroll
        for (int j = 0; j < 8; j++) {
            int col = warp_n*64 + j*8 + q2;
            if (col >= n_out) continue;
            float bx = 0.f, by = 0.f;
            if (bias) { float2 bb = *(const float2*)(bias + col); bx = bb.x; by = bb.y; }
            if (row0 < M) {
                float2 o = make_float2(acc[i][j][0] + bx, acc[i][j][1] + by);
                if (act) { o.x = lrelu(o.x); o.y = lrelu(o.y); }
                *(float2*)(C + (size_t)row0*ldc + col) = o;
            }
            if (row0 + 8 < M) {
                float2 o = make_float2(acc[i][j][2] + bx, acc[i][j][3] + by);
                if (act) { o.x = lrelu(o.x); o.y = lrelu(o.y); }
                *(float2*)(C + (size_t)(row0+8)*ldc + col) = o;
            }
        }
    }
}

// ---------------- fused small GEMM: RA (M=200) then TA (M=365) ----------------
__global__ void ra_ta_kernel(const float* __restrict__ rel_emb, const float* __restrict__ time_e,
                             const float* __restrict__ W_rt){
    int idx = blockIdx.x*blockDim.x + threadIdx.x;
    int total = (NUM_REL + NUM_TS) * 128;
    if (idx >= total) return;
    int row = idx >> 7, col = idx & 127;
    const float* a; const float* B; float* C;
    if (row < NUM_REL) { a = rel_emb + row*64;           B = W_rt;          C = &g_RA[row*DIM + col]; }
    else { int r2 = row - NUM_REL; a = time_e + r2*64;   B = W_rt + 64*128; C = &g_TA[r2*DIM + col]; }
    float s = 0.f;
    #pragma unroll
    for (int k = 0; k < 64; k++) s = fmaf(__ldg(a + k), __ldg(B + k*128 + col), s);
    *C = s;
}

// ---------------- all 4 weight transposes + splits in one launch ----------------
__global__ void wsplit_all_kernel(const float* __restrict__ W_fc, const float* __restrict__ W_node){
    int idx = blockIdx.x*blockDim.x + threadIdx.x;
    if (idx >= 4*16384) return;
    int which = idx >> 14, sub = idx & 16383;
    int n = sub >> 7, k = sub & 127;
    float v;
    if (which < 3) v = W_fc[(size_t)which*128*128 + k*128 + n];
    else           v = (n < 64) ? W_node[k*64 + n] : 0.f;
    __nv_bfloat16 h = __float2bfloat16(v);
    g_WT[(size_t)which*2*16384 + sub]         = h;
    g_WT[(size_t)which*2*16384 + 16384 + sub] = __float2bfloat16(v - __bfloat162float(h));
}

// ---------------- CSR build ----------------
__global__ void hist_kernel(const int* __restrict__ dst){
    int e = blockIdx.x*blockDim.x + threadIdx.x;
    if (e < EE) atomicAdd(&G_DEG[dst[e]], 1);
}

__global__ void scan_kernel(){
    __shared__ int warp_sums[32];
    __shared__ int s_carry;
    int tid = threadIdx.x;
    int lane = tid & 31, wid = tid >> 5;
    if (tid == 0) s_carry = 0;
    __syncthreads();
    for (int base = 0; base < NN; base += 1024){
        int i = base + tid;
        int v = (i < NN) ? G_DEG[i] : 0;
        int x = v;
        #pragma unroll
        for (int d = 1; d < 32; d <<= 1){
            int y = __shfl_up_sync(0xffffffffu, x, d);
            if (lane >= d) x += y;
        }
        if (lane == 31) warp_sums[wid] = x;
        __syncthreads();
        if (tid < 32){
            int w = warp_sums[tid];
            #pragma unroll
            for (int d = 1; d < 32; d <<= 1){
                int y = __shfl_up_sync(0xffffffffu, w, d);
                if (tid >= d) w += y;
            }
            warp_sums[tid] = w;
        }
        __syncthreads();
        int prefix = s_carry + (wid ? warp_sums[wid-1] : 0);
        if (i < NN) g_off[i] = x + prefix - v;   // exclusive
        __syncthreads();
        if (tid == 0) s_carry += warp_sums[31];
        __syncthreads();
    }
    if (threadIdx.x == 0) g_off[NN] = s_carry;
}

__global__ void scatter_kernel(const int* __restrict__ src, const int* __restrict__ dst,
                               const int* __restrict__ rel, const int* __restrict__ ts){
    int e = blockIdx.x*blockDim.x + threadIdx.x;
    if (e >= EE) return;
    int d = dst[e];
    int pos = g_off[d] + atomicAdd(&G_CUR[d], 1);
    g_srcS[pos]  = src[e];
    g_pairS[pos] = rel[e]*NUM_TS + ts[e];
}

// deterministic ordering within each segment
__global__ void sortseg_kernel(){
    int n = blockIdx.x*blockDim.x + threadIdx.x;
    if (n >= NN) return;
    int beg = g_off[n], end = g_off[n+1];
    for (int i = beg + 1; i < end; i++){
        int s = g_srcS[i], p = g_pairS[i];
        long long key = ((long long)s << 17) | p;
        int j = i - 1;
        while (j >= beg){
            long long kj = ((long long)g_srcS[j] << 17) | g_pairS[j];
            if (kj <= key) break;
            g_srcS[j+1] = g_srcS[j];
            g_pairS[j+1] = g_pairS[j];
            j--;
        }
        g_srcS[j+1] = s; g_pairS[j+1] = p;
    }
}

__global__ void qmask_kernel(const int* __restrict__ qo){
    int b = threadIdx.x;
    if (b < QB) {
        int n = qo[b];
        G_QM[n] = 1;
        G_TQ[n >> 7] = 1;
    }
}

// ---------------- fused aggregate: x[n] += mean_e lrelu(Y1[src]+R2T[pair]+Y3[n]) ----------------
__global__ __launch_bounds__(256) void aggregate_kernel(int masked){
    int w = (blockIdx.x*blockDim.x + threadIdx.x) >> 5;
    int lane = threadIdx.x & 31;
    if (w >= NN) return;
    if (masked && G_QM[w] == 0) return;
    int beg = g_off[w], end = g_off[w+1];
    if (beg == end) return;
    int c = lane << 2;
    float4 y3 = *(const float4*)&g_Y3[(size_t)w*DIM + c];
    float4 acc = make_float4(0.f,0.f,0.f,0.f);
    int i = beg;
    for (; i + 1 < end; i += 2){
        int s0 = g_srcS[i],   p0 = g_pairS[i];
        int s1 = g_srcS[i+1], p1 = g_pairS[i+1];
        float4 a0 = *(const float4*)&g_Y1[(size_t)s0*DIM + c];
        float4 b0 = *(const float4*)&g_R2T[(size_t)p0*DIM + c];
        float4 a1 = *(const float4*)&g_Y1[(size_t)s1*DIM + c];
        float4 b1 = *(const float4*)&g_R2T[(size_t)p1*DIM + c];
        acc.x += lrelu(a0.x + b0.x + y3.x);
        acc.y += lrelu(a0.y + b0.y + y3.y);
        acc.z += lrelu(a0.z + b0.z + y3.z);
        acc.w += lrelu(a0.w + b0.w + y3.w);
        acc.x += lrelu(a1.x + b1.x + y3.x);
        acc.y += lrelu(a1.y + b1.y + y3.y);
        acc.z += lrelu(a1.z + b1.z + y3.z);
        acc.w += lrelu(a1.w + b1.w + y3.w);
    }
    if (i < end){
        int s0 = g_srcS[i], p0 = g_pairS[i];
        float4 a0 = *(const float4*)&g_Y1[(size_t)s0*DIM + c];
        float4 b0 = *(const float4*)&g_R2T[(size_t)p0*DIM + c];
        acc.x += lrelu(a0.x + b0.x + y3.x);
        acc.y += lrelu(a0.y + b0.y + y3.y);
        acc.z += lrelu(a0.z + b0.z + y3.z);
        acc.w += lrelu(a0.w + b0.w + y3.w);
    }
    float inv = 1.f / (float)(end - beg);
    float4* xp = (float4*)&g_x[(size_t)w*DIM + c];
    float4 xv = *xp;
    xv.x += acc.x*inv; xv.y += acc.y*inv; xv.z += acc.z*inv; xv.w += acc.w*inv;
    *xp = xv;
}

// ---------------- prediction ----------------
__global__ void predict_kernel(const int* __restrict__ qs, const int* __restrict__ qo,
                               const int* __restrict__ qr, const int* __restrict__ qt,
                               const float* __restrict__ b_rt, const float* __restrict__ wp,
                               const float* __restrict__ bp, float* __restrict__ out){
    int w = (blockIdx.x*blockDim.x + threadIdx.x) >> 5;
    int lane = threadIdx.x & 31;
    if (w >= QB) return;
    int s = qs[w], o = qo[w], r = qr[w], t = qt[w];
    int c = lane << 2;
    float4 ra = *(const float4*)&g_RA[r*DIM + c];
    float4 ta = *(const float4*)&g_TA[t*DIM + c];
    float4 bb = *(const float4*)(b_rt + c);
    float q0 = lrelu(ra.x + ta.x + bb.x);
    float q1 = lrelu(ra.y + ta.y + bb.y);
    float q2 = lrelu(ra.z + ta.z + bb.z);
    float q3 = lrelu(ra.w + ta.w + bb.w);
    float4 xs = *(const float4*)&g_x[(size_t)s*DIM + c];
    float4 xo = *(const float4*)&g_x[(size_t)o*DIM + c];
    float4 w1 = *(const float4*)(wp + c);
    float4 w2 = *(const float4*)(wp + 128 + c);
    float4 w3 = *(const float4*)(wp + 256 + c);
    float sum = xs.x*w1.x + xs.y*w1.y + xs.z*w1.z + xs.w*w1.w
              + q0*w2.x + q1*w2.y + q2*w2.z + q3*w2.w
              + xo.x*w3.x + xo.y*w3.y + xo.z*w3.z + xo.w*w3.w;
    #pragma unroll
    for (int d = 16; d; d >>= 1) sum += __shfl_xor_sync(0xffffffffu, sum, d);
    if (lane == 0) out[w] = 1.f / (1.f + expf(-(sum + bp[0])));
}

// ---------------- host ----------------
extern "C" void kernel_launch(void* const* d_in, const int* in_sizes, int n_in,
                              void* d_out, int out_size){
    (void)in_sizes; (void)n_in; (void)out_size;
    const float* x_feat  = (const float*)d_in[0];
    const float* grp     = (const float*)d_in[1];
    const float* rel_emb = (const float*)d_in[2];
    const float* time_e  = (const float*)d_in[3];
    const float* W_node  = (const float*)d_in[4];
    const float* b_node  = (const float*)d_in[5];
    const float* W_rt    = (const float*)d_in[6];
    const float* b_rt    = (const float*)d_in[7];
    const float* W_fc    = (const float*)d_in[8];
    const float* b_fc    = (const float*)d_in[9];
    const float* w_pred  = (const float*)d_in[10];
    const float* b_pred  = (const float*)d_in[11];
    const int* node_ent  = (const int*)d_in[12];
    const int* edge_src  = (const int*)d_in[13];
    const int* edge_dst  = (const int*)d_in[14];
    const int* edge_type = (const int*)d_in[15];
    const int* edge_ts   = (const int*)d_in[16];
    const int* q_s = (const int*)d_in[17];
    const int* q_o = (const int*)d_in[18];
    const int* q_r = (const int*)d_in[19];
    const int* q_t = (const int*)d_in[20];
    float* out = (float*)d_out;

    float *px, *py1, *py3, *pr2t;
    __nv_bfloat16 *pWT;
    void *p_iscr; int *p_tq;
    cudaGetSymbolAddress((void**)&px,    g_x);
    cudaGetSymbolAddress((void**)&py1,   g_Y1);
    cudaGetSymbolAddress((void**)&py3,   g_Y3);
    cudaGetSymbolAddress((void**)&pr2t,  g_R2T);
    cudaGetSymbolAddress((void**)&pWT,   g_WT);
    cudaGetSymbolAddress(&p_iscr, g_iscr);
    p_tq = (int*)p_iscr + 3*NN;

    cudaFuncSetAttribute(hmma_gemm_kernel, cudaFuncAttributeMaxDynamicSharedMemorySize, MMA_SMEM_BYTES);

    // one memset covers deg / cursor / qmask / tile flags
    cudaMemsetAsync(p_iscr, 0, (3*NN + NTILE)*sizeof(int));

    __nv_bfloat16* W1t0 = pWT + 0*16384;  __nv_bfloat16* W1t1 = pWT + 1*16384;
    __nv_bfloat16* W2t0 = pWT + 2*16384;  __nv_bfloat16* W2t1 = pWT + 3*16384;
    __nv_bfloat16* W3t0 = pWT + 4*16384;  __nv_bfloat16* W3t1 = pWT + 5*16384;
    __nv_bfloat16* Wnt0 = pWT + 6*16384;  __nv_bfloat16* Wnt1 = pWT + 7*16384;

    // weights + small tables + masks
    wsplit_all_kernel<<<(4*16384 + 255)/256, 256>>>(W_fc, W_node);
    ra_ta_kernel<<<((NUM_REL+NUM_TS)*128 + 255)/256, 256>>>(rel_emb, time_e, W_rt);
    qmask_kernel<<<1, 256>>>(q_o);

    // node init: x[:,0:64] = lrelu(x_feat @ W_node + b_node); x[:,64:128] = grp gather (fused)
    hmma_gemm_kernel<<<dim3(NTILE,1), 256, MMA_SMEM_BYTES>>>(
        x_feat, 0, (const float*)0,
        Wnt0, Wnt1, px, b_node,  (const __nv_bfloat16*)0, (const __nv_bfloat16*)0, (float*)0, (const float*)0,
        DIM, NN, 64, 1, grp, node_ent, (const int*)0);

    // R2T = lrelu(RA+TA+b_rt) @ W_fc[128:256] + b_fc   (RELT generated in-kernel)
    hmma_gemm_kernel<<<dim3((NPAIR+127)/128,1), 256, MMA_SMEM_BYTES>>>(
        (const float*)0, 1, b_rt,
        W2t0, W2t1, pr2t, b_fc,  (const __nv_bfloat16*)0, (const __nv_bfloat16*)0, (float*)0, (const float*)0,
        DIM, NPAIR, 128, 0, (const float*)0, (const int*)0, (const int*)0);

    // CSR by dst (deterministic after segment sort)
    hist_kernel<<<(EE+255)/256, 256>>>(edge_dst);
    scan_kernel<<<1, 1024>>>();
    scatter_kernel<<<(EE+255)/256, 256>>>(edge_src, edge_dst, edge_type, edge_ts);
    sortseg_kernel<<<(NN+255)/256, 256>>>();

    // 2 full hops + 1 masked final hop; Y1 & Y3 in one launch (gridDim.y = 2)
    for (int hop = 0; hop < 3; hop++){
        const int* tf = (hop == 2) ? p_tq : (const int*)0;
        hmma_gemm_kernel<<<dim3(NTILE,2), 256, MMA_SMEM_BYTES>>>(
            px, 0, (const float*)0,
            W1t0, W1t1, py1, (const float*)0,
            W3t0, W3t1, py3, (const float*)0,
            DIM, NN, 128, 0, (const float*)0, (const int*)0, tf);
        aggregate_kernel<<<(NN*32 + 255)/256, 256>>>(hop == 2 ? 1 : 0);
    }

    predict_kernel<<<(QB*32 + 255)/256, 256>>>(q_s, q_o, q_r, q_t, b_rt, w_pred, b_pred, out);
}

// round 9
// speedup vs baseline: 1.7311x; 1.0033x over previous
#include <cuda_runtime.h>
#include <cuda_bf16.h>
#include <math.h>
#include <stdint.h>

// Problem constants (fixed by the dataset instance)
#define NN 20000          // nodes
#define EE 200000         // edges
#define QB 256            // queries
#define NUM_REL 200
#define NUM_TS 365
#define NPAIR (NUM_REL*NUM_TS)   // 73000
#define DIM 128           // 2h
#define NTILE ((NN+127)/128)     // 157 row tiles

// ---------------- scratch (static device globals; no allocation) ----------------
__device__ __align__(128) float g_x[NN*DIM];        // node state
__device__ __align__(128) float g_Y1[NN*DIM];       // x @ W_fc[0:128]
__device__ __align__(128) float g_Y3[NN*DIM];       // x @ W_fc[256:384]
__device__ __align__(128) float g_RA[NUM_REL*DIM];  // rel_emb @ W_rt[0:64]
__device__ __align__(128) float g_TA[NUM_TS*DIM];   // time_emb @ W_rt[64:128]
__device__ __align__(128) float g_R2T[NPAIR*DIM];   // lrelu(RA+TA+b_rt) @ W_fc[128:256] + b_fc

// transposed weight splits, each [128 n-rows][128 k-cols] bf16 (zero padded):
// 0:W1t0 1:W1t1 2:W2t0 3:W2t1 4:W3t0 5:W3t1 6:Wnt0 7:Wnt1
__device__ __align__(128) __nv_bfloat16 g_WT[8*16384];

// contiguous int scratch: [deg NN][cursor NN][qmask NN][tileq NTILE]
__device__ int g_iscr[3*NN + NTILE];
#define G_DEG (g_iscr)
#define G_CUR (g_iscr + NN)
#define G_QM  (g_iscr + 2*NN)
#define G_TQ  (g_iscr + 3*NN)

__device__ int g_off[NN+1];
__device__ int g_srcS[EE];
__device__ int g_pairS[EE];

__device__ __forceinline__ float lrelu(float v){ return fmaxf(v,0.f) + 0.2f*fminf(v,0.f); }

__device__ __forceinline__ uint32_t smem_u32(const void* p){
    uint32_t a;
    asm("{ .reg .u64 t; cvta.to.shared.u64 t, %1; cvt.u32.u64 %0, t; }" : "=r"(a) : "l"(p));
    return a;
}

// ============================================================================
// HMMA bf16x3 GEMM: C[M, n_out] = A_fp32[M,128] @ ((B0+B1)[n][k])^T
// A split in-kernel into bf16 hi/lo (or generated on the fly for RELT mode).
// Fragments loaded via ldmatrix.m8n8.x4 (6 LDSM vs 24 LDS per warp-k-step).
// gridDim.y selects (B,C,bias) pair -> one launch does Y1 and Y3.
// blockIdx.y==1 + tflags -> per-tile early exit (final-hop masked Y3).
// One CTA per 128-row tile; 8 warps in 4(m) x 2(n); warp tile 32x64.
// ============================================================================
#define GPAD 136   // bf16 elements per smem row (128 + 8 pad -> conflict-free)
#define MMA_SMEM_BYTES (4*128*GPAD*2)   // A0,A1,B0,B1 tiles = 139264 B

__device__ __forceinline__ void mma16816(float* c, const uint32_t* a, const uint32_t* b){
    asm volatile(
        "mma.sync.aligned.m16n8k16.row.col.f32.bf16.bf16.f32 "
        "{%0,%1,%2,%3}, {%4,%5,%6,%7}, {%8,%9}, {%0,%1,%2,%3};"
        : "+f"(c[0]), "+f"(c[1]), "+f"(c[2]), "+f"(c[3])
        : "r"(a[0]), "r"(a[1]), "r"(a[2]), "r"(a[3]), "r"(b[0]), "r"(b[1]));
}

__device__ __forceinline__ void ldsm_x4(uint32_t& r0, uint32_t& r1, uint32_t& r2, uint32_t& r3,
                                        uint32_t addr){
    asm volatile("ldmatrix.sync.aligned.m8n8.x4.shared.b16 {%0,%1,%2,%3}, [%4];"
        : "=r"(r0), "=r"(r1), "=r"(r2), "=r"(r3) : "r"(addr));
}

__device__ __forceinline__ void split_store(float4 v, __nv_bfloat16* d0, __nv_bfloat16* d1){
    __nv_bfloat16 h0=__float2bfloat16(v.x), h1=__float2bfloat16(v.y),
                  h2=__float2bfloat16(v.z), h3=__float2bfloat16(v.w);
    *(__nv_bfloat162*)(d0+0) = __halves2bfloat162(h0,h1);
    *(__nv_bfloat162*)(d0+2) = __halves2bfloat162(h2,h3);
    *(__nv_bfloat162*)(d1+0) = __halves2bfloat162(
        __float2bfloat16(v.x-__bfloat162float(h0)), __float2bfloat16(v.y-__bfloat162float(h1)));
    *(__nv_bfloat162*)(d1+2) = __halves2bfloat162(
        __float2bfloat16(v.z-__bfloat162float(h2)), __float2bfloat16(v.w-__bfloat162float(h3)));
}

__global__ __launch_bounds__(256, 1) void hmma_gemm_kernel(
    const float* __restrict__ A, int amode, const float* __restrict__ b_rt,
    const __nv_bfloat16* __restrict__ B0a, const __nv_bfloat16* __restrict__ B1a,
    float* __restrict__ Ca, const float* __restrict__ biasA,
    const __nv_bfloat16* __restrict__ B0b, const __nv_bfloat16* __restrict__ B1b,
    float* __restrict__ Cb, const float* __restrict__ biasB,
    int ldc, int M, int n_out, int act,
    const float* __restrict__ grp, const int* __restrict__ ent,
    const int* __restrict__ tflags)
{
    const int which = blockIdx.y;
    if (tflags && which == 1 && tflags[blockIdx.x] == 0) return;
    const __nv_bfloat16* Bt0 = which ? B0b : B0a;
    const __nv_bfloat16* Bt1 = which ? B1b : B1a;
    float* C = which ? Cb : Ca;
    const float* bias = which ? biasB : biasA;

    extern __shared__ __align__(16) char smem[];
    __nv_bfloat16* sA0 = (__nv_bfloat16*)smem;
    __nv_bfloat16* sA1 = sA0 + 128*GPAD;
    __nv_bfloat16* sB0 = sA1 + 128*GPAD;
    __nv_bfloat16* sB1 = sB0 + 128*GPAD;

    const int tid = threadIdx.x;
    const int wid = tid >> 5, lane = tid & 31;
    const int bm = blockIdx.x * 128;

    // ---- fill A (fp32 -> bf16 hi/lo split); amode 1 = RELT rows on the fly ----
    #pragma unroll
    for (int t = 0; t < 16; t++) {
        int idx = tid + t*256;               // 4096 float4 slots
        int row = idx >> 5, c4 = (idx & 31) << 2;
        float4 v = make_float4(0.f,0.f,0.f,0.f);
        int gr = bm + row;
        if (gr < M) {
            if (amode == 0) {
                v = *(const float4*)(A + (size_t)gr*128 + c4);
            } else {
                int r_ = gr / NUM_TS, t_ = gr - r_*NUM_TS;
                float4 ra = *(const float4*)&g_RA[r_*DIM + c4];
                float4 ta = *(const float4*)&g_TA[t_*DIM + c4];
                float4 bb = *(const float4*)(b_rt + c4);
                v.x = lrelu(ra.x + ta.x + bb.x);
                v.y = lrelu(ra.y + ta.y + bb.y);
                v.z = lrelu(ra.z + ta.z + bb.z);
                v.w = lrelu(ra.w + ta.w + bb.w);
            }
        }
        split_store(v, sA0 + row*GPAD + c4, sA1 + row*GPAD + c4);
    }
    // ---- fill B tiles (already bf16, [n][k] row-major) ----
    #pragma unroll
    for (int t = 0; t < 8; t++) {
        int idx = tid + t*256;               // 2048 float4 (8-bf16) slots
        int row = idx >> 4, c8 = (idx & 15) << 3;
        *(float4*)(sB0 + row*GPAD + c8) = *(const float4*)(Bt0 + (size_t)row*128 + c8);
        *(float4*)(sB1 + row*GPAD + c8) = *(const float4*)(Bt1 + (size_t)row*128 + c8);
    }
    // ---- fused grp gather (node-init only): x[:,64:128] = grp[ent] ----
    if (ent) {
        #pragma unroll
        for (int t = 0; t < 8; t++) {
            int idx = tid + t*256;           // 2048 float4
            int row = idx >> 4, c4 = (idx & 15) << 2;
            int gr = bm + row;
            if (gr < M)
                *(float4*)(Ca + (size_t)gr*ldc + 64 + c4) =
                    *(const float4*)(grp + (size_t)ent[gr]*64 + c4);
        }
    }
    __syncthreads();

    const int warp_m = wid & 3;              // 0..3 -> m offset 32*warp_m
    const int warp_n = wid >> 2;             // 0..1 -> n offset 64*warp_n
    const int gid = lane >> 2;               // 0..7
    const int q2  = (lane & 3) << 1;         // 0,2,4,6

    // ldmatrix lane-address offsets (bf16 elements), layout derived to match the
    // m16n8k16 fragment ownership exactly (see round notes):
    //   A x4: groups {m0+ri, m0+8+ri} x {k0, k0+8}
    //   B x4: groups {nj+ri, nj+8+ri} x {k0, k0+8}  (two j-blocks per ldmatrix)
    const int g8 = lane >> 3, ri = lane & 7;
    const uint32_t sbase = smem_u32(smem);
    const uint32_t uA0 = sbase;
    const uint32_t uA1 = sbase + 128*GPAD*2;
    const uint32_t uB0 = sbase + 2*128*GPAD*2;
    const uint32_t uB1 = sbase + 3*128*GPAD*2;
    const uint32_t aoff = (uint32_t)(((g8 & 1)*8 + ri)*GPAD + (g8 >> 1)*8);
    const uint32_t boff = (uint32_t)(((g8 >> 1)*8 + ri)*GPAD + (g8 & 1)*8);
    const uint32_t aAddr0 = (uint32_t)((warp_m*32)*GPAD) + aoff;        // i=0
    const uint32_t aAddr1 = aAddr0 + 16*GPAD;                            // i=1
    uint32_t bAddr[4];
    #pragma unroll
    for (int jj = 0; jj < 4; jj++)
        bAddr[jj] = (uint32_t)((warp_n*64 + jj*16)*GPAD) + boff;

    float acc[2][8][4];
    #pragma unroll
    for (int i = 0; i < 2; i++)
        #pragma unroll
        for (int j = 0; j < 8; j++)
            #pragma unroll
            for (int q = 0; q < 4; q++) acc[i][j][q] = 0.f;

    #pragma unroll 1
    for (int p = 0; p < 3; p++) {
        const uint32_t Ab = (p == 2) ? uA1 : uA0;
        const uint32_t Bb = (p == 1) ? uB1 : uB0;
        #pragma unroll
        for (int ks = 0; ks < 8; ks++) {
            const uint32_t koff = (uint32_t)ks * 32u;   // 16 bf16 = 32 bytes
            uint32_t a[2][4];
            ldsm_x4(a[0][0], a[0][1], a[0][2], a[0][3], Ab + aAddr0*2 + koff);
            ldsm_x4(a[1][0], a[1][1], a[1][2], a[1][3], Ab + aAddr1*2 + koff);
            uint32_t b[8][2];
            #pragma unroll
            for (int jj = 0; jj < 4; jj++)
                ldsm_x4(b[2*jj][0], b[2*jj][1], b[2*jj+1][0], b[2*jj+1][1],
                        Bb + bAddr[jj]*2 + koff);
            #pragma unroll
            for (int i = 0; i < 2; i++)
                #pragma unroll
                for (int j = 0; j < 8; j++)
                    mma16816(acc[i][j], a[i], b[j]);
        }
    }

    // ---- epilogue ----
    #pragma unroll
    for (int i = 0; i < 2; i++) {
        int row0 = bm + warp_m*32 + i*16 + gid;
        #pragma unroll
        for (int j = 0; j < 8; j++) {
            int col = warp_n*64 + j*8 + q2;
            if (col >= n_out) continue;
            float bx = 0.f, by = 0.f;
            if (bias) { float2 bb = *(const float2*)(bias + col); bx = bb.x; by = bb.y; }
            if (row0 < M) {
                float2 o = make_float2(acc[i][j][0] + bx, acc[i][j][1] + by);
                if (act) { o.x = lrelu(o.x); o.y = lrelu(o.y); }
                *(float2*)(C + (size_t)row0*ldc + col) = o;
            }
            if (row0 + 8 < M) {
                float2 o = make_float2(acc[i][j][2] + bx, acc[i][j][3] + by);
                if (act) { o.x = lrelu(o.x); o.y = lrelu(o.y); }
                *(float2*)(C + (size_t)(row0+8)*ldc + col) = o;
            }
        }
    }
}

// ---------------- fused small GEMM: RA (M=200) then TA (M=365) ----------------
__global__ void ra_ta_kernel(const float* __restrict__ rel_emb, const float* __restrict__ time_e,
                             const float* __restrict__ W_rt){
    int idx = blockIdx.x*blockDim.x + threadIdx.x;
    int total = (NUM_REL + NUM_TS) * 128;
    if (idx >= total) return;
    int row = idx >> 7, col = idx & 127;
    const float* a; const float* B; float* C;
    if (row < NUM_REL) { a = rel_emb + row*64;           B = W_rt;          C = &g_RA[row*DIM + col]; }
    else { int r2 = row - NUM_REL; a = time_e + r2*64;   B = W_rt + 64*128; C = &g_TA[r2*DIM + col]; }
    float s = 0.f;
    #pragma unroll
    for (int k = 0; k < 64; k++) s = fmaf(__ldg(a + k), __ldg(B + k*128 + col), s);
    *C = s;
}

// ---------------- all 4 weight transposes + splits in one launch ----------------
__global__ void wsplit_all_kernel(const float* __restrict__ W_fc, const float* __restrict__ W_node){
    int idx = blockIdx.x*blockDim.x + threadIdx.x;
    if (idx >= 4*16384) return;
    int which = idx >> 14, sub = idx & 16383;
    int n = sub >> 7, k = sub & 127;
    float v;
    if (which < 3) v = W_fc[(size_t)which*128*128 + k*128 + n];
    else           v = (n < 64) ? W_node[k*64 + n] : 0.f;
    __nv_bfloat16 h = __float2bfloat16(v);
    g_WT[(size_t)which*2*16384 + sub]         = h;
    g_WT[(size_t)which*2*16384 + 16384 + sub] = __float2bfloat16(v - __bfloat162float(h));
}

// ---------------- CSR build ----------------
__global__ void hist_kernel(const int* __restrict__ dst){
    int e = blockIdx.x*blockDim.x + threadIdx.x;
    if (e < EE) atomicAdd(&G_DEG[dst[e]], 1);
}

__global__ void scan_kernel(){
    __shared__ int warp_sums[32];
    __shared__ int s_carry;
    int tid = threadIdx.x;
    int lane = tid & 31, wid = tid >> 5;
    if (tid == 0) s_carry = 0;
    __syncthreads();
    for (int base = 0; base < NN; base += 1024){
        int i = base + tid;
        int v = (i < NN) ? G_DEG[i] : 0;
        int x = v;
        #pragma unroll
        for (int d = 1; d < 32; d <<= 1){
            int y = __shfl_up_sync(0xffffffffu, x, d);
            if (lane >= d) x += y;
        }
        if (lane == 31) warp_sums[wid] = x;
        __syncthreads();
        if (tid < 32){
            int w = warp_sums[tid];
            #pragma unroll
            for (int d = 1; d < 32; d <<= 1){
                int y = __shfl_up_sync(0xffffffffu, w, d);
                if (tid >= d) w += y;
            }
            warp_sums[tid] = w;
        }
        __syncthreads();
        int prefix = s_carry + (wid ? warp_sums[wid-1] : 0);
        if (i < NN) g_off[i] = x + prefix - v;   // exclusive
        __syncthreads();
        if (tid == 0) s_carry += warp_sums[31];
        __syncthreads();
    }
    if (threadIdx.x == 0) g_off[NN] = s_carry;
}

__global__ void scatter_kernel(const int* __restrict__ src, const int* __restrict__ dst,
                               const int* __restrict__ rel, const int* __restrict__ ts){
    int e = blockIdx.x*blockDim.x + threadIdx.x;
    if (e >= EE) return;
    int d = dst[e];
    int pos = g_off[d] + atomicAdd(&G_CUR[d], 1);
    g_srcS[pos]  = src[e];
    g_pairS[pos] = rel[e]*NUM_TS + ts[e];
}

// deterministic ordering within each segment
__global__ void sortseg_kernel(){
    int n = blockIdx.x*blockDim.x + threadIdx.x;
    if (n >= NN) return;
    int beg = g_off[n], end = g_off[n+1];
    for (int i = beg + 1; i < end; i++){
        int s = g_srcS[i], p = g_pairS[i];
        long long key = ((long long)s << 17) | p;
        int j = i - 1;
        while (j >= beg){
            long long kj = ((long long)g_srcS[j] << 17) | g_pairS[j];
            if (kj <= key) break;
            g_srcS[j+1] = g_srcS[j];
            g_pairS[j+1] = g_pairS[j];
            j--;
        }
        g_srcS[j+1] = s; g_pairS[j+1] = p;
    }
}

__global__ void qmask_kernel(const int* __restrict__ qo){
    int b = threadIdx.x;
    if (b < QB) {
        int n = qo[b];
        G_QM[n] = 1;
        G_TQ[n >> 7] = 1;
    }
}

// ---------------- fused aggregate: x[n] += mean_e lrelu(Y1[src]+R2T[pair]+Y3[n]) ----------------
__global__ __launch_bounds__(256) void aggregate_kernel(int masked){
    int w = (blockIdx.x*blockDim.x + threadIdx.x) >> 5;
    int lane = threadIdx.x & 31;
    if (w >= NN) return;
    if (masked && G_QM[w] == 0) return;
    int beg = g_off[w], end = g_off[w+1];
    if (beg == end) return;
    int c = lane << 2;
    float4 y3 = *(const float4*)&g_Y3[(size_t)w*DIM + c];
    float4 acc = make_float4(0.f,0.f,0.f,0.f);
    int i = beg;
    for (; i + 1 < end; i += 2){
        int s0 = g_srcS[i],   p0 = g_pairS[i];
        int s1 = g_srcS[i+1], p1 = g_pairS[i+1];
        float4 a0 = *(const float4*)&g_Y1[(size_t)s0*DIM + c];
        float4 b0 = *(const float4*)&g_R2T[(size_t)p0*DIM + c];
        float4 a1 = *(const float4*)&g_Y1[(size_t)s1*DIM + c];
        float4 b1 = *(const float4*)&g_R2T[(size_t)p1*DIM + c];
        acc.x += lrelu(a0.x + b0.x + y3.x);
        acc.y += lrelu(a0.y + b0.y + y3.y);
        acc.z += lrelu(a0.z + b0.z + y3.z);
        acc.w += lrelu(a0.w + b0.w + y3.w);
        acc.x += lrelu(a1.x + b1.x + y3.x);
        acc.y += lrelu(a1.y + b1.y + y3.y);
        acc.z += lrelu(a1.z + b1.z + y3.z);
        acc.w += lrelu(a1.w + b1.w + y3.w);
    }
    if (i < end){
        int s0 = g_srcS[i], p0 = g_pairS[i];
        float4 a0 = *(const float4*)&g_Y1[(size_t)s0*DIM + c];
        float4 b0 = *(const float4*)&g_R2T[(size_t)p0*DIM + c];
        acc.x += lrelu(a0.x + b0.x + y3.x);
        acc.y += lrelu(a0.y + b0.y + y3.y);
        acc.z += lrelu(a0.z + b0.z + y3.z);
        acc.w += lrelu(a0.w + b0.w + y3.w);
    }
    float inv = 1.f / (float)(end - beg);
    float4* xp = (float4*)&g_x[(size_t)w*DIM + c];
    float4 xv = *xp;
    xv.x += acc.x*inv; xv.y += acc.y*inv; xv.z += acc.z*inv; xv.w += acc.w*inv;
    *xp = xv;
}

// ---------------- prediction ----------------
__global__ void predict_kernel(const int* __restrict__ qs, const int* __restrict__ qo,
                               const int* __restrict__ qr, const int* __restrict__ qt,
                               const float* __restrict__ b_rt, const float* __restrict__ wp,
                               const float* __restrict__ bp, float* __restrict__ out){
    int w = (blockIdx.x*blockDim.x + threadIdx.x) >> 5;
    int lane = threadIdx.x & 31;
    if (w >= QB) return;
    int s = qs[w], o = qo[w], r = qr[w], t = qt[w];
    int c = lane << 2;
    float4 ra = *(const float4*)&g_RA[r*DIM + c];
    float4 ta = *(const float4*)&g_TA[t*DIM + c];
    float4 bb = *(const float4*)(b_rt + c);
    float q0 = lrelu(ra.x + ta.x + bb.x);
    float q1 = lrelu(ra.y + ta.y + bb.y);
    float q2 = lrelu(ra.z + ta.z + bb.z);
    float q3 = lrelu(ra.w + ta.w + bb.w);
    float4 xs = *(const float4*)&g_x[(size_t)s*DIM + c];
    float4 xo = *(const float4*)&g_x[(size_t)o*DIM + c];
    float4 w1 = *(const float4*)(wp + c);
    float4 w2 = *(const float4*)(wp + 128 + c);
    float4 w3 = *(const float4*)(wp + 256 + c);
    float sum = xs.x*w1.x + xs.y*w1.y + xs.z*w1.z + xs.w*w1.w
              + q0*w2.x + q1*w2.y + q2*w2.z + q3*w2.w
              + xo.x*w3.x + xo.y*w3.y + xo.z*w3.z + xo.w*w3.w;
    #pragma unroll
    for (int d = 16; d; d >>= 1) sum += __shfl_xor_sync(0xffffffffu, sum, d);
    if (lane == 0) out[w] = 1.f / (1.f + expf(-(sum + bp[0])));
}

// ---------------- host ----------------
extern "C" void kernel_launch(void* const* d_in, const int* in_sizes, int n_in,
                              void* d_out, int out_size){
    (void)in_sizes; (void)n_in; (void)out_size;
    const float* x_feat  = (const float*)d_in[0];
    const float* grp     = (const float*)d_in[1];
    const float* rel_emb = (const float*)d_in[2];
    const float* time_e  = (const float*)d_in[3];
    const float* W_node  = (const float*)d_in[4];
    const float* b_node  = (const float*)d_in[5];
    const float* W_rt    = (const float*)d_in[6];
    const float* b_rt    = (const float*)d_in[7];
    const float* W_fc    = (const float*)d_in[8];
    const float* b_fc    = (const float*)d_in[9];
    const float* w_pred  = (const float*)d_in[10];
    const float* b_pred  = (const float*)d_in[11];
    const int* node_ent  = (const int*)d_in[12];
    const int* edge_src  = (const int*)d_in[13];
    const int* edge_dst  = (const int*)d_in[14];
    const int* edge_type = (const int*)d_in[15];
    const int* edge_ts   = (const int*)d_in[16];
    const int* q_s = (const int*)d_in[17];
    const int* q_o = (const int*)d_in[18];
    const int* q_r = (const int*)d_in[19];
    const int* q_t = (const int*)d_in[20];
    float* out = (float*)d_out;

    float *px, *py1, *py3, *pr2t;
    __nv_bfloat16 *pWT;
    void *p_iscr; int *p_tq;
    cudaGetSymbolAddress((void**)&px,    g_x);
    cudaGetSymbolAddress((void**)&py1,   g_Y1);
    cudaGetSymbolAddress((void**)&py3,   g_Y3);
    cudaGetSymbolAddress((void**)&pr2t,  g_R2T);
    cudaGetSymbolAddress((void**)&pWT,   g_WT);
    cudaGetSymbolAddress(&p_iscr, g_iscr);
    p_tq = (int*)p_iscr + 3*NN;

    cudaFuncSetAttribute(hmma_gemm_kernel, cudaFuncAttributeMaxDynamicSharedMemorySize, MMA_SMEM_BYTES);

    // one memset covers deg / cursor / qmask / tile flags
    cudaMemsetAsync(p_iscr, 0, (3*NN + NTILE)*sizeof(int));

    __nv_bfloat16* W1t0 = pWT + 0*16384;  __nv_bfloat16* W1t1 = pWT + 1*16384;
    __nv_bfloat16* W2t0 = pWT + 2*16384;  __nv_bfloat16* W2t1 = pWT + 3*16384;
    __nv_bfloat16* W3t0 = pWT + 4*16384;  __nv_bfloat16* W3t1 = pWT + 5*16384;
    __nv_bfloat16* Wnt0 = pWT + 6*16384;  __nv_bfloat16* Wnt1 = pWT + 7*16384;

    // weights + small tables + masks
    wsplit_all_kernel<<<(4*16384 + 255)/256, 256>>>(W_fc, W_node);
    ra_ta_kernel<<<((NUM_REL+NUM_TS)*128 + 255)/256, 256>>>(rel_emb, time_e, W_rt);
    qmask_kernel<<<1, 256>>>(q_o);

    // node init: x[:,0:64] = lrelu(x_feat @ W_node + b_node); x[:,64:128] = grp gather (fused)
    hmma_gemm_kernel<<<dim3(NTILE,1), 256, MMA_SMEM_BYTES>>>(
        x_feat, 0, (const float*)0,
        Wnt0, Wnt1, px, b_node,  (const __nv_bfloat16*)0, (const __nv_bfloat16*)0, (float*)0, (const float*)0,
        DIM, NN, 64, 1, grp, node_ent, (const int*)0);

    // R2T = lrelu(RA+TA+b_rt) @ W_fc[128:256] + b_fc   (RELT generated in-kernel)
    hmma_gemm_kernel<<<dim3((NPAIR+127)/128,1), 256, MMA_SMEM_BYTES>>>(
        (const float*)0, 1, b_rt,
        W2t0, W2t1, pr2t, b_fc,  (const __nv_bfloat16*)0, (const __nv_bfloat16*)0, (float*)0, (const float*)0,
        DIM, NPAIR, 128, 0, (const float*)0, (const int*)0, (const int*)0);

    // CSR by dst (deterministic after segment sort)
    hist_kernel<<<(EE+255)/256, 256>>>(edge_dst);
    scan_kernel<<<1, 1024>>>();
    scatter_kernel<<<(EE+255)/256, 256>>>(edge_src, edge_dst, edge_type, edge_ts);
    sortseg_kernel<<<(NN+255)/256, 256>>>();

    // 2 full hops + 1 masked final hop; Y1 & Y3 in one launch (gridDim.y = 2)
    for (int hop = 0; hop < 3; hop++){
        const int* tf = (hop == 2) ? p_tq : (const int*)0;
        hmma_gemm_kernel<<<dim3(NTILE,2), 256, MMA_SMEM_BYTES>>>(
            px, 0, (const float*)0,
            W1t0, W1t1, py1, (const float*)0,
            W3t0, W3t1, py3, (const float*)0,
            DIM, NN, 128, 0, (const float*)0, (const int*)0, tf);
        aggregate_kernel<<<(NN*32 + 255)/256, 256>>>(hop == 2 ? 1 : 0);
    }

    predict_kernel<<<(QB*32 + 255)/256, 256>>>(q_s, q_o, q_r, q_t, b_rt, w_pred, b_pred, out);
}

// round 10
// speedup vs baseline: 1.8747x; 1.0829x over previous
#include <cuda_runtime.h>
#include <cuda_bf16.h>
#include <math.h>
#include <stdint.h>

// Problem constants (fixed by the dataset instance)
#define NN 20000          // nodes
#define EE 200000         // edges
#define QB 256            // queries
#define NUM_REL 200
#define NUM_TS 365
#define NPAIR (NUM_REL*NUM_TS)   // 73000
#define DIM 128           // 2h
#define MT 64             // GEMM M-tile rows (64 -> 2 CTAs/SM)
#define NT64 ((NN+63)/64)        // 313 row tiles over nodes

// ---------------- scratch (static device globals; no allocation) ----------------
__device__ __align__(128) float g_x[NN*DIM];        // node state
__device__ __align__(128) float g_Y1[NN*DIM];       // x @ W_fc[0:128]
__device__ __align__(128) float g_Y3[NN*DIM];       // x @ W_fc[256:384]
__device__ __align__(128) float g_RA[NUM_REL*DIM];  // rel_emb @ W_rt[0:64]
__device__ __align__(128) float g_TA[NUM_TS*DIM];   // time_emb @ W_rt[64:128]
__device__ __align__(128) float g_R2T[NPAIR*DIM];   // lrelu(RA+TA+b_rt) @ W_fc[128:256] + b_fc

// transposed weight splits, each [128 n-rows][128 k-cols] bf16 (zero padded):
// 0:W1t0 1:W1t1 2:W2t0 3:W2t1 4:W3t0 5:W3t1 6:Wnt0 7:Wnt1
__device__ __align__(128) __nv_bfloat16 g_WT[8*16384];

// contiguous int scratch: [deg NN][cursor NN][qmask NN][tileq NT64]
__device__ int g_iscr[3*NN + NT64];
#define G_DEG (g_iscr)
#define G_CUR (g_iscr + NN)
#define G_QM  (g_iscr + 2*NN)
#define G_TQ  (g_iscr + 3*NN)

__device__ int g_off[NN+1];
__device__ int g_srcS[EE];
__device__ int g_pairS[EE];

__device__ __forceinline__ float lrelu(float v){ return fmaxf(v,0.f) + 0.2f*fminf(v,0.f); }

__device__ __forceinline__ uint32_t smem_u32(const void* p){
    uint32_t a;
    asm("{ .reg .u64 t; cvta.to.shared.u64 t, %1; cvt.u32.u64 %0, t; }" : "=r"(a) : "l"(p));
    return a;
}

// ============================================================================
// HMMA bf16x3 GEMM: C[M, n_out] = A_fp32[M,128] @ ((B0+B1)[n][k])^T
// 64x128 CTA tile -> 104 KB smem -> 2 CTAs/SM (16 warps; fill/epilogue of one
// CTA overlaps the mainloop of the other). 8 warps in 2(m) x 4(n), warp tile
// 32x32. Fragments via ldmatrix.m8n8.x4 (layout validated in R9: rel_err
// bit-identical to scalar-LDS path).
// ============================================================================
#define GPAD 136   // bf16 elements per smem row (128 + 8 pad; 272B stride, 16B-aligned)
#define MMA_SMEM_BYTES ((2*MT + 2*128)*GPAD*2)   // A0,A1 (64 rows) + B0,B1 (128 rows) = 104448 B

__device__ __forceinline__ void mma16816(float* c, const uint32_t* a, const uint32_t* b){
    asm volatile(
        "mma.sync.aligned.m16n8k16.row.col.f32.bf16.bf16.f32 "
        "{%0,%1,%2,%3}, {%4,%5,%6,%7}, {%8,%9}, {%0,%1,%2,%3};"
        : "+f"(c[0]), "+f"(c[1]), "+f"(c[2]), "+f"(c[3])
        : "r"(a[0]), "r"(a[1]), "r"(a[2]), "r"(a[3]), "r"(b[0]), "r"(b[1]));
}

__device__ __forceinline__ void ldsm_x4(uint32_t& r0, uint32_t& r1, uint32_t& r2, uint32_t& r3,
                                        uint32_t addr){
    asm volatile("ldmatrix.sync.aligned.m8n8.x4.shared.b16 {%0,%1,%2,%3}, [%4];"
        : "=r"(r0), "=r"(r1), "=r"(r2), "=r"(r3) : "r"(addr));
}

__device__ __forceinline__ void split_store(float4 v, __nv_bfloat16* d0, __nv_bfloat16* d1){
    __nv_bfloat16 h0=__float2bfloat16(v.x), h1=__float2bfloat16(v.y),
                  h2=__float2bfloat16(v.z), h3=__float2bfloat16(v.w);
    *(__nv_bfloat162*)(d0+0) = __halves2bfloat162(h0,h1);
    *(__nv_bfloat162*)(d0+2) = __halves2bfloat162(h2,h3);
    *(__nv_bfloat162*)(d1+0) = __halves2bfloat162(
        __float2bfloat16(v.x-__bfloat162float(h0)), __float2bfloat16(v.y-__bfloat162float(h1)));
    *(__nv_bfloat162*)(d1+2) = __halves2bfloat162(
        __float2bfloat16(v.z-__bfloat162float(h2)), __float2bfloat16(v.w-__bfloat162float(h3)));
}

__global__ __launch_bounds__(256, 2) void hmma_gemm_kernel(
    const float* __restrict__ A, int amode, const float* __restrict__ b_rt,
    const __nv_bfloat16* __restrict__ B0a, const __nv_bfloat16* __restrict__ B1a,
    float* __restrict__ Ca, const float* __restrict__ biasA,
    const __nv_bfloat16* __restrict__ B0b, const __nv_bfloat16* __restrict__ B1b,
    float* __restrict__ Cb, const float* __restrict__ biasB,
    int ldc, int M, int n_out, int act,
    const float* __restrict__ grp, const int* __restrict__ ent,
    const int* __restrict__ tflags)
{
    const int which = blockIdx.y;
    if (tflags && which == 1 && tflags[blockIdx.x] == 0) return;
    const __nv_bfloat16* Bt0 = which ? B0b : B0a;
    const __nv_bfloat16* Bt1 = which ? B1b : B1a;
    float* C = which ? Cb : Ca;
    const float* bias = which ? biasB : biasA;

    extern __shared__ __align__(16) char smem[];
    __nv_bfloat16* sA0 = (__nv_bfloat16*)smem;              // MT x GPAD
    __nv_bfloat16* sA1 = sA0 + MT*GPAD;                      // MT x GPAD
    __nv_bfloat16* sB0 = sA1 + MT*GPAD;                      // 128 x GPAD
    __nv_bfloat16* sB1 = sB0 + 128*GPAD;                     // 128 x GPAD

    const int tid = threadIdx.x;
    const int wid = tid >> 5, lane = tid & 31;
    const int bm = blockIdx.x * MT;

    // ---- fill A (fp32 -> bf16 hi/lo split); amode 1 = RELT rows on the fly ----
    #pragma unroll
    for (int t = 0; t < 8; t++) {
        int idx = tid + t*256;               // MT*32 = 2048 float4 slots
        int row = idx >> 5, c4 = (idx & 31) << 2;
        float4 v = make_float4(0.f,0.f,0.f,0.f);
        int gr = bm + row;
        if (gr < M) {
            if (amode == 0) {
                v = *(const float4*)(A + (size_t)gr*128 + c4);
            } else {
                int r_ = gr / NUM_TS, t_ = gr - r_*NUM_TS;
                float4 ra = *(const float4*)&g_RA[r_*DIM + c4];
                float4 ta = *(const float4*)&g_TA[t_*DIM + c4];
                float4 bb = *(const float4*)(b_rt + c4);
                v.x = lrelu(ra.x + ta.x + bb.x);
                v.y = lrelu(ra.y + ta.y + bb.y);
                v.z = lrelu(ra.z + ta.z + bb.z);
                v.w = lrelu(ra.w + ta.w + bb.w);
            }
        }
        split_store(v, sA0 + row*GPAD + c4, sA1 + row*GPAD + c4);
    }
    // ---- fill B tiles (already bf16, [n][k] row-major) ----
    #pragma unroll
    for (int t = 0; t < 8; t++) {
        int idx = tid + t*256;               // 2048 float4 (8-bf16) slots
        int row = idx >> 4, c8 = (idx & 15) << 3;
        *(float4*)(sB0 + row*GPAD + c8) = *(const float4*)(Bt0 + (size_t)row*128 + c8);
        *(float4*)(sB1 + row*GPAD + c8) = *(const float4*)(Bt1 + (size_t)row*128 + c8);
    }
    // ---- fused grp gather (node-init only): x[:,64:128] = grp[ent] ----
    if (ent) {
        #pragma unroll
        for (int t = 0; t < 4; t++) {
            int idx = tid + t*256;           // MT*16 = 1024 float4
            int row = idx >> 4, c4 = (idx & 15) << 2;
            int gr = bm + row;
            if (gr < M)
                *(float4*)(Ca + (size_t)gr*ldc + 64 + c4) =
                    *(const float4*)(grp + (size_t)ent[gr]*64 + c4);
        }
    }
    __syncthreads();

    const int warp_m = wid & 1;              // 0..1 -> m offset 32*warp_m
    const int warp_n = wid >> 1;             // 0..3 -> n offset 32*warp_n
    const int gid = lane >> 2;               // 0..7
    const int q2  = (lane & 3) << 1;         // 0,2,4,6

    // ldmatrix lane-address offsets (bf16 elements) — same formulas as R9
    // (validated: rel_err identical to scalar-LDS path).
    const int g8 = lane >> 3, ri = lane & 7;
    const uint32_t sbase = smem_u32(smem);
    const uint32_t uA0 = sbase;
    const uint32_t uA1 = sbase + MT*GPAD*2;
    const uint32_t uB0 = sbase + 2*MT*GPAD*2;
    const uint32_t uB1 = uB0 + 128*GPAD*2;
    const uint32_t aoff = (uint32_t)(((g8 & 1)*8 + ri)*GPAD + (g8 >> 1)*8);
    const uint32_t boff = (uint32_t)(((g8 >> 1)*8 + ri)*GPAD + (g8 & 1)*8);
    const uint32_t aAddr0 = (uint32_t)((warp_m*32)*GPAD) + aoff;        // i=0
    const uint32_t aAddr1 = aAddr0 + 16*GPAD;                            // i=1
    uint32_t bAddr[2];
    #pragma unroll
    for (int jj = 0; jj < 2; jj++)
        bAddr[jj] = (uint32_t)((warp_n*32 + jj*16)*GPAD) + boff;

    float acc[2][4][4];
    #pragma unroll
    for (int i = 0; i < 2; i++)
        #pragma unroll
        for (int j = 0; j < 4; j++)
            #pragma unroll
            for (int q = 0; q < 4; q++) acc[i][j][q] = 0.f;

    #pragma unroll 1
    for (int p = 0; p < 3; p++) {
        const uint32_t Ab = (p == 2) ? uA1 : uA0;
        const uint32_t Bb = (p == 1) ? uB1 : uB0;
        #pragma unroll
        for (int ks = 0; ks < 8; ks++) {
            const uint32_t koff = (uint32_t)ks * 32u;   // 16 bf16 = 32 bytes
            uint32_t a[2][4];
            ldsm_x4(a[0][0], a[0][1], a[0][2], a[0][3], Ab + aAddr0*2 + koff);
            ldsm_x4(a[1][0], a[1][1], a[1][2], a[1][3], Ab + aAddr1*2 + koff);
            uint32_t b[4][2];
            #pragma unroll
            for (int jj = 0; jj < 2; jj++)
                ldsm_x4(b[2*jj][0], b[2*jj][1], b[2*jj+1][0], b[2*jj+1][1],
                        Bb + bAddr[jj]*2 + koff);
            #pragma unroll
            for (int i = 0; i < 2; i++)
                #pragma unroll
                for (int j = 0; j < 4; j++)
                    mma16816(acc[i][j], a[i], b[j]);
        }
    }

    // ---- epilogue ----
    #pragma unroll
    for (int i = 0; i < 2; i++) {
        int row0 = bm + warp_m*32 + i*16 + gid;
        #pragma unroll
        for (int j = 0; j < 4; j++) {
            int col = warp_n*32 + j*8 + q2;
            if (col >= n_out) continue;
            float bx = 0.f, by = 0.f;
            if (bias) { float2 bb = *(const float2*)(bias + col); bx = bb.x; by = bb.y; }
            if (row0 < M) {
                float2 o = make_float2(acc[i][j][0] + bx, acc[i][j][1] + by);
                if (act) { o.x = lrelu(o.x); o.y = lrelu(o.y); }
                *(float2*)(C + (size_t)row0*ldc + col) = o;
            }
            if (row0 + 8 < M) {
                float2 o = make_float2(acc[i][j][2] + bx, acc[i][j][3] + by);
                if (act) { o.x = lrelu(o.x); o.y = lrelu(o.y); }
                *(float2*)(C + (size_t)(row0+8)*ldc + col) = o;
            }
        }
    }
}

// ---------------- fused small GEMM: RA (M=200) then TA (M=365) ----------------
__global__ void ra_ta_kernel(const float* __restrict__ rel_emb, const float* __restrict__ time_e,
                             const float* __restrict__ W_rt){
    int idx = blockIdx.x*blockDim.x + threadIdx.x;
    int total = (NUM_REL + NUM_TS) * 128;
    if (idx >= total) return;
    int row = idx >> 7, col = idx & 127;
    const float* a; const float* B; float* C;
    if (row < NUM_REL) { a = rel_emb + row*64;           B = W_rt;          C = &g_RA[row*DIM + col]; }
    else { int r2 = row - NUM_REL; a = time_e + r2*64;   B = W_rt + 64*128; C = &g_TA[r2*DIM + col]; }
    float s = 0.f;
    #pragma unroll
    for (int k = 0; k < 64; k++) s = fmaf(__ldg(a + k), __ldg(B + k*128 + col), s);
    *C = s;
}

// ---------------- all 4 weight transposes + splits in one launch ----------------
__global__ void wsplit_all_kernel(const float* __restrict__ W_fc, const float* __restrict__ W_node){
    int idx = blockIdx.x*blockDim.x + threadIdx.x;
    if (idx >= 4*16384) return;
    int which = idx >> 14, sub = idx & 16383;
    int n = sub >> 7, k = sub & 127;
    float v;
    if (which < 3) v = W_fc[(size_t)which*128*128 + k*128 + n];
    else           v = (n < 64) ? W_node[k*64 + n] : 0.f;
    __nv_bfloat16 h = __float2bfloat16(v);
    g_WT[(size_t)which*2*16384 + sub]         = h;
    g_WT[(size_t)which*2*16384 + 16384 + sub] = __float2bfloat16(v - __bfloat162float(h));
}

// ---------------- CSR build ----------------
__global__ void hist_kernel(const int* __restrict__ dst){
    int e = blockIdx.x*blockDim.x + threadIdx.x;
    if (e < EE) atomicAdd(&G_DEG[dst[e]], 1);
}

__global__ void scan_kernel(){
    __shared__ int warp_sums[32];
    __shared__ int s_carry;
    int tid = threadIdx.x;
    int lane = tid & 31, wid = tid >> 5;
    if (tid == 0) s_carry = 0;
    __syncthreads();
    for (int base = 0; base < NN; base += 1024){
        int i = base + tid;
        int v = (i < NN) ? G_DEG[i] : 0;
        int x = v;
        #pragma unroll
        for (int d = 1; d < 32; d <<= 1){
            int y = __shfl_up_sync(0xffffffffu, x, d);
            if (lane >= d) x += y;
        }
        if (lane == 31) warp_sums[wid] = x;
        __syncthreads();
        if (tid < 32){
            int w = warp_sums[tid];
            #pragma unroll
            for (int d = 1; d < 32; d <<= 1){
                int y = __shfl_up_sync(0xffffffffu, w, d);
                if (tid >= d) w += y;
            }
            warp_sums[tid] = w;
        }
        __syncthreads();
        int prefix = s_carry + (wid ? warp_sums[wid-1] : 0);
        if (i < NN) g_off[i] = x + prefix - v;   // exclusive
        __syncthreads();
        if (tid == 0) s_carry += warp_sums[31];
        __syncthreads();
    }
    if (threadIdx.x == 0) g_off[NN] = s_carry;
}

__global__ void scatter_kernel(const int* __restrict__ src, const int* __restrict__ dst,
                               const int* __restrict__ rel, const int* __restrict__ ts){
    int e = blockIdx.x*blockDim.x + threadIdx.x;
    if (e >= EE) return;
    int d = dst[e];
    int pos = g_off[d] + atomicAdd(&G_CUR[d], 1);
    g_srcS[pos]  = src[e];
    g_pairS[pos] = rel[e]*NUM_TS + ts[e];
}

// deterministic ordering within each segment
__global__ void sortseg_kernel(){
    int n = blockIdx.x*blockDim.x + threadIdx.x;
    if (n >= NN) return;
    int beg = g_off[n], end = g_off[n+1];
    for (int i = beg + 1; i < end; i++){
        int s = g_srcS[i], p = g_pairS[i];
        long long key = ((long long)s << 17) | p;
        int j = i - 1;
        while (j >= beg){
            long long kj = ((long long)g_srcS[j] << 17) | g_pairS[j];
            if (kj <= key) break;
            g_srcS[j+1] = g_srcS[j];
            g_pairS[j+1] = g_pairS[j];
            j--;
        }
        g_srcS[j+1] = s; g_pairS[j+1] = p;
    }
}

__global__ void qmask_kernel(const int* __restrict__ qo){
    int b = threadIdx.x;
    if (b < QB) {
        int n = qo[b];
        G_QM[n] = 1;
        G_TQ[n >> 6] = 1;    // 64-row GEMM tiles
    }
}

// ---------------- fused aggregate: x[n] += mean_e lrelu(Y1[src]+R2T[pair]+Y3[n]) ----------------
__global__ __launch_bounds__(256) void aggregate_kernel(int masked){
    int w = (blockIdx.x*blockDim.x + threadIdx.x) >> 5;
    int lane = threadIdx.x & 31;
    if (w >= NN) return;
    if (masked && G_QM[w] == 0) return;
    int beg = g_off[w], end = g_off[w+1];
    if (beg == end) return;
    int c = lane << 2;
    float4 y3 = *(const float4*)&g_Y3[(size_t)w*DIM + c];
    float4 acc = make_float4(0.f,0.f,0.f,0.f);
    int i = beg;
    for (; i + 1 < end; i += 2){
        int s0 = g_srcS[i],   p0 = g_pairS[i];
        int s1 = g_srcS[i+1], p1 = g_pairS[i+1];
        float4 a0 = *(const float4*)&g_Y1[(size_t)s0*DIM + c];
        float4 b0 = *(const float4*)&g_R2T[(size_t)p0*DIM + c];
        float4 a1 = *(const float4*)&g_Y1[(size_t)s1*DIM + c];
        float4 b1 = *(const float4*)&g_R2T[(size_t)p1*DIM + c];
        acc.x += lrelu(a0.x + b0.x + y3.x);
        acc.y += lrelu(a0.y + b0.y + y3.y);
        acc.z += lrelu(a0.z + b0.z + y3.z);
        acc.w += lrelu(a0.w + b0.w + y3.w);
        acc.x += lrelu(a1.x + b1.x + y3.x);
        acc.y += lrelu(a1.y + b1.y + y3.y);
        acc.z += lrelu(a1.z + b1.z + y3.z);
        acc.w += lrelu(a1.w + b1.w + y3.w);
    }
    if (i < end){
        int s0 = g_srcS[i], p0 = g_pairS[i];
        float4 a0 = *(const float4*)&g_Y1[(size_t)s0*DIM + c];
        float4 b0 = *(const float4*)&g_R2T[(size_t)p0*DIM + c];
        acc.x += lrelu(a0.x + b0.x + y3.x);
        acc.y += lrelu(a0.y + b0.y + y3.y);
        acc.z += lrelu(a0.z + b0.z + y3.z);
        acc.w += lrelu(a0.w + b0.w + y3.w);
    }
    float inv = 1.f / (float)(end - beg);
    float4* xp = (float4*)&g_x[(size_t)w*DIM + c];
    float4 xv = *xp;
    xv.x += acc.x*inv; xv.y += acc.y*inv; xv.z += acc.z*inv; xv.w += acc.w*inv;
    *xp = xv;
}

// ---------------- prediction ----------------
__global__ void predict_kernel(const int* __restrict__ qs, const int* __restrict__ qo,
                               const int* __restrict__ qr, const int* __restrict__ qt,
                               const float* __restrict__ b_rt, const float* __restrict__ wp,
                               const float* __restrict__ bp, float* __restrict__ out){
    int w = (blockIdx.x*blockDim.x + threadIdx.x) >> 5;
    int lane = threadIdx.x & 31;
    if (w >= QB) return;
    int s = qs[w], o = qo[w], r = qr[w], t = qt[w];
    int c = lane << 2;
    float4 ra = *(const float4*)&g_RA[r*DIM + c];
    float4 ta = *(const float4*)&g_TA[t*DIM + c];
    float4 bb = *(const float4*)(b_rt + c);
    float q0 = lrelu(ra.x + ta.x + bb.x);
    float q1 = lrelu(ra.y + ta.y + bb.y);
    float q2 = lrelu(ra.z + ta.z + bb.z);
    float q3 = lrelu(ra.w + ta.w + bb.w);
    float4 xs = *(const float4*)&g_x[(size_t)s*DIM + c];
    float4 xo = *(const float4*)&g_x[(size_t)o*DIM + c];
    float4 w1 = *(const float4*)(wp + c);
    float4 w2 = *(const float4*)(wp + 128 + c);
    float4 w3 = *(const float4*)(wp + 256 + c);
    float sum = xs.x*w1.x + xs.y*w1.y + xs.z*w1.z + xs.w*w1.w
              + q0*w2.x + q1*w2.y + q2*w2.z + q3*w2.w
              + xo.x*w3.x + xo.y*w3.y + xo.z*w3.z + xo.w*w3.w;
    #pragma unroll
    for (int d = 16; d; d >>= 1) sum += __shfl_xor_sync(0xffffffffu, sum, d);
    if (lane == 0) out[w] = 1.f / (1.f + expf(-(sum + bp[0])));
}

// ---------------- host ----------------
extern "C" void kernel_launch(void* const* d_in, const int* in_sizes, int n_in,
                              void* d_out, int out_size){
    (void)in_sizes; (void)n_in; (void)out_size;
    const float* x_feat  = (const float*)d_in[0];
    const float* grp     = (const float*)d_in[1];
    const float* rel_emb = (const float*)d_in[2];
    const float* time_e  = (const float*)d_in[3];
    const float* W_node  = (const float*)d_in[4];
    const float* b_node  = (const float*)d_in[5];
    const float* W_rt    = (const float*)d_in[6];
    const float* b_rt    = (const float*)d_in[7];
    const float* W_fc    = (const float*)d_in[8];
    const float* b_fc    = (const float*)d_in[9];
    const float* w_pred  = (const float*)d_in[10];
    const float* b_pred  = (const float*)d_in[11];
    const int* node_ent  = (const int*)d_in[12];
    const int* edge_src  = (const int*)d_in[13];
    const int* edge_dst  = (const int*)d_in[14];
    const int* edge_type = (const int*)d_in[15];
    const int* edge_ts   = (const int*)d_in[16];
    const int* q_s = (const int*)d_in[17];
    const int* q_o = (const int*)d_in[18];
    const int* q_r = (const int*)d_in[19];
    const int* q_t = (const int*)d_in[20];
    float* out = (float*)d_out;

    float *px, *py1, *py3, *pr2t;
    __nv_bfloat16 *pWT;
    void *p_iscr; int *p_tq;
    cudaGetSymbolAddress((void**)&px,    g_x);
    cudaGetSymbolAddress((void**)&py1,   g_Y1);
    cudaGetSymbolAddress((void**)&py3,   g_Y3);
    cudaGetSymbolAddress((void**)&pr2t,  g_R2T);
    cudaGetSymbolAddress((void**)&pWT,   g_WT);
    cudaGetSymbolAddress(&p_iscr, g_iscr);
    p_tq = (int*)p_iscr + 3*NN;

    cudaFuncSetAttribute(hmma_gemm_kernel, cudaFuncAttributeMaxDynamicSharedMemorySize, MMA_SMEM_BYTES);

    // one memset covers deg / cursor / qmask / tile flags
    cudaMemsetAsync(p_iscr, 0, (3*NN + NT64)*sizeof(int));

    __nv_bfloat16* W1t0 = pWT + 0*16384;  __nv_bfloat16* W1t1 = pWT + 1*16384;
    __nv_bfloat16* W2t0 = pWT + 2*16384;  __nv_bfloat16* W2t1 = pWT + 3*16384;
    __nv_bfloat16* W3t0 = pWT + 4*16384;  __nv_bfloat16* W3t1 = pWT + 5*16384;
    __nv_bfloat16* Wnt0 = pWT + 6*16384;  __nv_bfloat16* Wnt1 = pWT + 7*16384;

    // weights + small tables + masks
    wsplit_all_kernel<<<(4*16384 + 255)/256, 256>>>(W_fc, W_node);
    ra_ta_kernel<<<((NUM_REL+NUM_TS)*128 + 255)/256, 256>>>(rel_emb, time_e, W_rt);
    qmask_kernel<<<1, 256>>>(q_o);

    // node init: x[:,0:64] = lrelu(x_feat @ W_node + b_node); x[:,64:128] = grp gather (fused)
    hmma_gemm_kernel<<<dim3(NT64,1), 256, MMA_SMEM_BYTES>>>(
        x_feat, 0, (const float*)0,
        Wnt0, Wnt1, px, b_node,  (const __nv_bfloat16*)0, (const __nv_bfloat16*)0, (float*)0, (const float*)0,
        DIM, NN, 64, 1, grp, node_ent, (const int*)0);

    // R2T = lrelu(RA+TA+b_rt) @ W_fc[128:256] + b_fc   (RELT generated in-kernel)
    hmma_gemm_kernel<<<dim3((NPAIR+MT-1)/MT,1), 256, MMA_SMEM_BYTES>>>(
        (const float*)0, 1, b_rt,
        W2t0, W2t1, pr2t, b_fc,  (const __nv_bfloat16*)0, (const __nv_bfloat16*)0, (float*)0, (const float*)0,
        DIM, NPAIR, 128, 0, (const float*)0, (const int*)0, (const int*)0);

    // CSR by dst (deterministic after segment sort)
    hist_kernel<<<(EE+255)/256, 256>>>(edge_dst);
    scan_kernel<<<1, 1024>>>();
    scatter_kernel<<<(EE+255)/256, 256>>>(edge_src, edge_dst, edge_type, edge_ts);
    sortseg_kernel<<<(NN+255)/256, 256>>>();

    // 2 full hops + 1 masked final hop; Y1 & Y3 in one launch (gridDim.y = 2)
    for (int hop = 0; hop < 3; hop++){
        const int* tf = (hop == 2) ? p_tq : (const int*)0;
        hmma_gemm_kernel<<<dim3(NT64,2), 256, MMA_SMEM_BYTES>>>(
            px, 0, (const float*)0,
            W1t0, W1t1, py1, (const float*)0,
            W3t0, W3t1, py3, (const float*)0,
            DIM, NN, 128, 0, (const float*)0, (const int*)0, tf);
        aggregate_kernel<<<(NN*32 + 255)/256, 256>>>(hop == 2 ? 1 : 0);
    }

    predict_kernel<<<(QB*32 + 255)/256, 256>>>(q_s, q_o, q_r, q_t, b_rt, w_pred, b_pred, out);
}

// round 12
// speedup vs baseline: 2.1455x; 1.1445x over previous
#include <cuda_runtime.h>
#include <cuda_bf16.h>
#include <math.h>
#include <stdint.h>

// Problem constants (fixed by the dataset instance)
#define NN 20000          // nodes
#define EE 200000         // edges
#define QB 256            // queries
#define NUM_REL 200
#define NUM_TS 365
#define NPAIR (NUM_REL*NUM_TS)   // 73000
#define DIM 128           // 2h
#define MT 64             // GEMM M-tile rows (64 -> 2 CTAs/SM)
#define NT64 ((NN+63)/64)        // 313 row tiles over nodes

// ---------------- scratch (static device globals; no allocation) ----------------
__device__ __align__(128) float g_x[NN*DIM];        // node state
__device__ __align__(128) float g_Y1[NN*DIM];       // x @ W_fc[0:128]
__device__ __align__(128) float g_Y3[NN*DIM];       // x @ W_fc[256:384]
__device__ __align__(128) float g_RA[NUM_REL*DIM];  // rel_emb @ W_rt[0:64]
__device__ __align__(128) float g_TA[NUM_TS*DIM];   // time_emb @ W_rt[64:128]
__device__ __align__(128) float g_R2T[NPAIR*DIM];   // lrelu(RA+TA+b_rt) @ W_fc[128:256] + b_fc

// transposed weight splits, each [128 n-rows][128 k-cols] bf16 (zero padded):
// 0:W1t0 1:W1t1 2:W2t0 3:W2t1 4:W3t0 5:W3t1 6:Wnt0 7:Wnt1
__device__ __align__(128) __nv_bfloat16 g_WT[8*16384];

// contiguous int scratch: [deg NN][cursor NN][qmask NN][tileq NT64]
__device__ int g_iscr[3*NN + NT64];
#define G_DEG (g_iscr)
#define G_CUR (g_iscr + NN)
#define G_QM  (g_iscr + 2*NN)
#define G_TQ  (g_iscr + 3*NN)

__device__ int g_off[NN+1];
__device__ int g_srcS[EE];
__device__ int g_pairS[EE];

__device__ __forceinline__ float lrelu(float v){ return fmaxf(v,0.f) + 0.2f*fminf(v,0.f); }

__device__ __forceinline__ uint32_t smem_u32(const void* p){
    uint32_t a;
    asm("{ .reg .u64 t; cvta.to.shared.u64 t, %1; cvt.u32.u64 %0, t; }" : "=r"(a) : "l"(p));
    return a;
}

// ============================================================================
// HMMA bf16x3 GEMM: C[M, n_out] = A_fp32[M,128] @ ((B0+B1)[n][k])^T
// 64x128 CTA tile -> 104 KB smem -> 2 CTAs/SM. B fill via cp.async (overlaps
// with A fill's LDG+convert). 8 warps in 2(m) x 4(n), warp tile 32x32.
// Fragments via ldmatrix.m8n8.x4 (layout validated: rel_err bit-identical).
// ============================================================================
#define GPAD 136   // bf16 elements per smem row (128 + 8 pad; 272B stride, 16B-aligned)
#define MMA_SMEM_BYTES ((2*MT + 2*128)*GPAD*2)   // A0,A1 (64 rows) + B0,B1 (128 rows) = 104448 B

__device__ __forceinline__ void mma16816(float* c, const uint32_t* a, const uint32_t* b){
    asm volatile(
        "mma.sync.aligned.m16n8k16.row.col.f32.bf16.bf16.f32 "
        "{%0,%1,%2,%3}, {%4,%5,%6,%7}, {%8,%9}, {%0,%1,%2,%3};"
        : "+f"(c[0]), "+f"(c[1]), "+f"(c[2]), "+f"(c[3])
        : "r"(a[0]), "r"(a[1]), "r"(a[2]), "r"(a[3]), "r"(b[0]), "r"(b[1]));
}

__device__ __forceinline__ void ldsm_x4(uint32_t& r0, uint32_t& r1, uint32_t& r2, uint32_t& r3,
                                        uint32_t addr){
    asm volatile("ldmatrix.sync.aligned.m8n8.x4.shared.b16 {%0,%1,%2,%3}, [%4];"
        : "=r"(r0), "=r"(r1), "=r"(r2), "=r"(r3) : "r"(addr));
}

__device__ __forceinline__ void cp_async16(uint32_t smem_dst, const void* gsrc){
    asm volatile("cp.async.ca.shared.global [%0], [%1], 16;"
        :: "r"(smem_dst), "l"(gsrc) : "memory");
}

__device__ __forceinline__ void split_store(float4 v, __nv_bfloat16* d0, __nv_bfloat16* d1){
    __nv_bfloat16 h0=__float2bfloat16(v.x), h1=__float2bfloat16(v.y),
                  h2=__float2bfloat16(v.z), h3=__float2bfloat16(v.w);
    *(__nv_bfloat162*)(d0+0) = __halves2bfloat162(h0,h1);
    *(__nv_bfloat162*)(d0+2) = __halves2bfloat162(h2,h3);
    *(__nv_bfloat162*)(d1+0) = __halves2bfloat162(
        __float2bfloat16(v.x-__bfloat162float(h0)), __float2bfloat16(v.y-__bfloat162float(h1)));
    *(__nv_bfloat162*)(d1+2) = __halves2bfloat162(
        __float2bfloat16(v.z-__bfloat162float(h2)), __float2bfloat16(v.w-__bfloat162float(h3)));
}

__global__ __launch_bounds__(256, 2) void hmma_gemm_kernel(
    const float* __restrict__ A, int amode, const float* __restrict__ b_rt,
    const __nv_bfloat16* __restrict__ B0a, const __nv_bfloat16* __restrict__ B1a,
    float* __restrict__ Ca, const float* __restrict__ biasA,
    const __nv_bfloat16* __restrict__ B0b, const __nv_bfloat16* __restrict__ B1b,
    float* __restrict__ Cb, const float* __restrict__ biasB,
    int ldc, int M, int n_out, int act,
    const float* __restrict__ grp, const int* __restrict__ ent,
    const int* __restrict__ tflags)
{
    const int which = blockIdx.y;
    if (tflags && which == 1 && tflags[blockIdx.x] == 0) return;
    const __nv_bfloat16* Bt0 = which ? B0b : B0a;
    const __nv_bfloat16* Bt1 = which ? B1b : B1a;
    float* C = which ? Cb : Ca;
    const float* bias = which ? biasB : biasA;

    extern __shared__ __align__(16) char smem[];
    __nv_bfloat16* sA0 = (__nv_bfloat16*)smem;              // MT x GPAD
    __nv_bfloat16* sA1 = sA0 + MT*GPAD;                      // MT x GPAD

    const int tid = threadIdx.x;
    const int wid = tid >> 5, lane = tid & 31;
    const int bm = blockIdx.x * MT;

    const uint32_t sbase = smem_u32(smem);
    const uint32_t uA0 = sbase;
    const uint32_t uA1 = sbase + MT*GPAD*2;
    const uint32_t uB0 = sbase + 2*MT*GPAD*2;
    const uint32_t uB1 = uB0 + 128*GPAD*2;

    // ---- B tiles via cp.async (issued FIRST; overlaps A's LDG+convert) ----
    #pragma unroll
    for (int t = 0; t < 8; t++) {
        int idx = tid + t*256;               // 2048 16B slots
        int row = idx >> 4, c8 = (idx & 15) << 3;
        uint32_t so = (uint32_t)(row*GPAD + c8) * 2u;
        cp_async16(uB0 + so, Bt0 + (size_t)row*128 + c8);
        cp_async16(uB1 + so, Bt1 + (size_t)row*128 + c8);
    }
    asm volatile("cp.async.commit_group;" ::: "memory");

    // ---- fill A (fp32 -> bf16 hi/lo split); amode 1 = RELT rows on the fly ----
    #pragma unroll
    for (int t = 0; t < 8; t++) {
        int idx = tid + t*256;               // MT*32 = 2048 float4 slots
        int row = idx >> 5, c4 = (idx & 31) << 2;
        float4 v = make_float4(0.f,0.f,0.f,0.f);
        int gr = bm + row;
        if (gr < M) {
            if (amode == 0) {
                v = *(const float4*)(A + (size_t)gr*128 + c4);
            } else {
                int r_ = gr / NUM_TS, t_ = gr - r_*NUM_TS;
                float4 ra = *(const float4*)&g_RA[r_*DIM + c4];
                float4 ta = *(const float4*)&g_TA[t_*DIM + c4];
                float4 bb = *(const float4*)(b_rt + c4);
                v.x = lrelu(ra.x + ta.x + bb.x);
                v.y = lrelu(ra.y + ta.y + bb.y);
                v.z = lrelu(ra.z + ta.z + bb.z);
                v.w = lrelu(ra.w + ta.w + bb.w);
            }
        }
        split_store(v, sA0 + row*GPAD + c4, sA1 + row*GPAD + c4);
    }
    // ---- fused grp gather (node-init only): x[:,64:128] = grp[ent] ----
    if (ent) {
        #pragma unroll
        for (int t = 0; t < 4; t++) {
            int idx = tid + t*256;           // MT*16 = 1024 float4
            int row = idx >> 4, c4 = (idx & 15) << 2;
            int gr = bm + row;
            if (gr < M)
                *(float4*)(Ca + (size_t)gr*ldc + 64 + c4) =
                    *(const float4*)(grp + (size_t)ent[gr]*64 + c4);
        }
    }
    asm volatile("cp.async.wait_group 0;" ::: "memory");
    __syncthreads();

    const int warp_m = wid & 1;              // 0..1 -> m offset 32*warp_m
    const int warp_n = wid >> 1;             // 0..3 -> n offset 32*warp_n
    const int gid = lane >> 2;               // 0..7
    const int q2  = (lane & 3) << 1;         // 0,2,4,6

    // ldmatrix lane-address offsets (bf16 elements) — validated layout
    const int g8 = lane >> 3, ri = lane & 7;
    const uint32_t aoff = (uint32_t)(((g8 & 1)*8 + ri)*GPAD + (g8 >> 1)*8);
    const uint32_t boff = (uint32_t)(((g8 >> 1)*8 + ri)*GPAD + (g8 & 1)*8);
    const uint32_t aAddr0 = (uint32_t)((warp_m*32)*GPAD) + aoff;        // i=0
    const uint32_t aAddr1 = aAddr0 + 16*GPAD;                            // i=1
    uint32_t bAddr[2];
    #pragma unroll
    for (int jj = 0; jj < 2; jj++)
        bAddr[jj] = (uint32_t)((warp_n*32 + jj*16)*GPAD) + boff;

    float acc[2][4][4];
    #pragma unroll
    for (int i = 0; i < 2; i++)
        #pragma unroll
        for (int j = 0; j < 4; j++)
            #pragma unroll
            for (int q = 0; q < 4; q++) acc[i][j][q] = 0.f;

    #pragma unroll 1
    for (int p = 0; p < 3; p++) {
        const uint32_t Ab = (p == 2) ? uA1 : uA0;
        const uint32_t Bb = (p == 1) ? uB1 : uB0;
        #pragma unroll
        for (int ks = 0; ks < 8; ks++) {
            const uint32_t koff = (uint32_t)ks * 32u;   // 16 bf16 = 32 bytes
            uint32_t a[2][4];
            ldsm_x4(a[0][0], a[0][1], a[0][2], a[0][3], Ab + aAddr0*2 + koff);
            ldsm_x4(a[1][0], a[1][1], a[1][2], a[1][3], Ab + aAddr1*2 + koff);
            uint32_t b[4][2];
            #pragma unroll
            for (int jj = 0; jj < 2; jj++)
                ldsm_x4(b[2*jj][0], b[2*jj][1], b[2*jj+1][0], b[2*jj+1][1],
                        Bb + bAddr[jj]*2 + koff);
            #pragma unroll
            for (int i = 0; i < 2; i++)
                #pragma unroll
                for (int j = 0; j < 4; j++)
                    mma16816(acc[i][j], a[i], b[j]);
        }
    }

    // ---- epilogue ----
    #pragma unroll
    for (int i = 0; i < 2; i++) {
        int row0 = bm + warp_m*32 + i*16 + gid;
        #pragma unroll
        for (int j = 0; j < 4; j++) {
            int col = warp_n*32 + j*8 + q2;
            if (col >= n_out) continue;
            float bx = 0.f, by = 0.f;
            if (bias) { float2 bb = *(const float2*)(bias + col); bx = bb.x; by = bb.y; }
            if (row0 < M) {
                float2 o = make_float2(acc[i][j][0] + bx, acc[i][j][1] + by);
                if (act) { o.x = lrelu(o.x); o.y = lrelu(o.y); }
                *(float2*)(C + (size_t)row0*ldc + col) = o;
            }
            if (row0 + 8 < M) {
                float2 o = make_float2(acc[i][j][2] + bx, acc[i][j][3] + by);
                if (act) { o.x = lrelu(o.x); o.y = lrelu(o.y); }
                *(float2*)(C + (size_t)(row0+8)*ldc + col) = o;
            }
        }
    }
}

// ---------------- fused small GEMM: RA (M=200) then TA (M=365) ----------------
__global__ void ra_ta_kernel(const float* __restrict__ rel_emb, const float* __restrict__ time_e,
                             const float* __restrict__ W_rt){
    int idx = blockIdx.x*blockDim.x + threadIdx.x;
    int total = (NUM_REL + NUM_TS) * 128;
    if (idx >= total) return;
    int row = idx >> 7, col = idx & 127;
    const float* a; const float* B; float* C;
    if (row < NUM_REL) { a = rel_emb + row*64;           B = W_rt;          C = &g_RA[row*DIM + col]; }
    else { int r2 = row - NUM_REL; a = time_e + r2*64;   B = W_rt + 64*128; C = &g_TA[r2*DIM + col]; }
    float s = 0.f;
    #pragma unroll
    for (int k = 0; k < 64; k++) s = fmaf(__ldg(a + k), __ldg(B + k*128 + col), s);
    *C = s;
}

// ---------------- all 4 weight transposes + splits in one launch ----------------
__global__ void wsplit_all_kernel(const float* __restrict__ W_fc, const float* __restrict__ W_node){
    int idx = blockIdx.x*blockDim.x + threadIdx.x;
    if (idx >= 4*16384) return;
    int which = idx >> 14, sub = idx & 16383;
    int n = sub >> 7, k = sub & 127;
    float v;
    if (which < 3) v = W_fc[(size_t)which*128*128 + k*128 + n];
    else           v = (n < 64) ? W_node[k*64 + n] : 0.f;
    __nv_bfloat16 h = __float2bfloat16(v);
    g_WT[(size_t)which*2*16384 + sub]         = h;
    g_WT[(size_t)which*2*16384 + 16384 + sub] = __float2bfloat16(v - __bfloat162float(h));
}

// ---------------- CSR build ----------------
__global__ void hist_kernel(const int* __restrict__ dst){
    int e = blockIdx.x*blockDim.x + threadIdx.x;
    if (e < EE) atomicAdd(&G_DEG[dst[e]], 1);
}

__global__ void scan_kernel(){
    __shared__ int warp_sums[32];
    __shared__ int s_carry;
    int tid = threadIdx.x;
    int lane = tid & 31, wid = tid >> 5;
    if (tid == 0) s_carry = 0;
    __syncthreads();
    for (int base = 0; base < NN; base += 1024){
        int i = base + tid;
        int v = (i < NN) ? G_DEG[i] : 0;
        int x = v;
        #pragma unroll
        for (int d = 1; d < 32; d <<= 1){
            int y = __shfl_up_sync(0xffffffffu, x, d);
            if (lane >= d) x += y;
        }
        if (lane == 31) warp_sums[wid] = x;
        __syncthreads();
        if (tid < 32){
            int w = warp_sums[tid];
            #pragma unroll
            for (int d = 1; d < 32; d <<= 1){
                int y = __shfl_up_sync(0xffffffffu, w, d);
                if (tid >= d) w += y;
            }
            warp_sums[tid] = w;
        }
        __syncthreads();
        int prefix = s_carry + (wid ? warp_sums[wid-1] : 0);
        if (i < NN) g_off[i] = x + prefix - v;   // exclusive
        __syncthreads();
        if (tid == 0) s_carry += warp_sums[31];
        __syncthreads();
    }
    if (threadIdx.x == 0) g_off[NN] = s_carry;
}

__global__ void scatter_kernel(const int* __restrict__ src, const int* __restrict__ dst,
                               const int* __restrict__ rel, const int* __restrict__ ts){
    int e = blockIdx.x*blockDim.x + threadIdx.x;
    if (e >= EE) return;
    int d = dst[e];
    int pos = g_off[d] + atomicAdd(&G_CUR[d], 1);
    g_srcS[pos]  = src[e];
    g_pairS[pos] = rel[e]*NUM_TS + ts[e];
}

// deterministic ordering within each segment
__global__ void sortseg_kernel(){
    int n = blockIdx.x*blockDim.x + threadIdx.x;
    if (n >= NN) return;
    int beg = g_off[n], end = g_off[n+1];
    for (int i = beg + 1; i < end; i++){
        int s = g_srcS[i], p = g_pairS[i];
        long long key = ((long long)s << 17) | p;
        int j = i - 1;
        while (j >= beg){
            long long kj = ((long long)g_srcS[j] << 17) | g_pairS[j];
            if (kj <= key) break;
            g_srcS[j+1] = g_srcS[j];
            g_pairS[j+1] = g_pairS[j];
            j--;
        }
        g_srcS[j+1] = s; g_pairS[j+1] = p;
    }
}

__global__ void qmask_kernel(const int* __restrict__ qo){
    int b = threadIdx.x;
    if (b < QB) {
        int n = qo[b];
        G_QM[n] = 1;
        G_TQ[n >> 6] = 1;    // 64-row GEMM tiles
    }
}

// ---------------- fused aggregate: x[n] += mean_e lrelu(Y1[src]+R2T[pair]+Y3[n]) ----------------
__global__ __launch_bounds__(256) void aggregate_kernel(int masked){
    int w = (blockIdx.x*blockDim.x + threadIdx.x) >> 5;
    int lane = threadIdx.x & 31;
    if (w >= NN) return;
    if (masked && G_QM[w] == 0) return;
    int beg = g_off[w], end = g_off[w+1];
    if (beg == end) return;
    int c = lane << 2;
    float4 y3 = *(const float4*)&g_Y3[(size_t)w*DIM + c];
    float4 acc = make_float4(0.f,0.f,0.f,0.f);
    int i = beg;
    for (; i + 1 < end; i += 2){
        int s0 = g_srcS[i],   p0 = g_pairS[i];
        int s1 = g_srcS[i+1], p1 = g_pairS[i+1];
        float4 a0 = *(const float4*)&g_Y1[(size_t)s0*DIM + c];
        float4 b0 = *(const float4*)&g_R2T[(size_t)p0*DIM + c];
        float4 a1 = *(const float4*)&g_Y1[(size_t)s1*DIM + c];
        float4 b1 = *(const float4*)&g_R2T[(size_t)p1*DIM + c];
        acc.x += lrelu(a0.x + b0.x + y3.x);
        acc.y += lrelu(a0.y + b0.y + y3.y);
        acc.z += lrelu(a0.z + b0.z + y3.z);
        acc.w += lrelu(a0.w + b0.w + y3.w);
        acc.x += lrelu(a1.x + b1.x + y3.x);
        acc.y += lrelu(a1.y + b1.y + y3.y);
        acc.z += lrelu(a1.z + b1.z + y3.z);
        acc.w += lrelu(a1.w + b1.w + y3.w);
    }
    if (i < end){
        int s0 = g_srcS[i], p0 = g_pairS[i];
        float4 a0 = *(const float4*)&g_Y1[(size_t)s0*DIM + c];
        float4 b0 = *(const float4*)&g_R2T[(size_t)p0*DIM + c];
        acc.x += lrelu(a0.x + b0.x + y3.x);
        acc.y += lrelu(a0.y + b0.y + y3.y);
        acc.z += lrelu(a0.z + b0.z + y3.z);
        acc.w += lrelu(a0.w + b0.w + y3.w);
    }
    float inv = 1.f / (float)(end - beg);
    float4* xp = (float4*)&g_x[(size_t)w*DIM + c];
    float4 xv = *xp;
    xv.x += acc.x*inv; xv.y += acc.y*inv; xv.z += acc.z*inv; xv.w += acc.w*inv;
    *xp = xv;
}

// ---------------- prediction ----------------
__global__ void predict_kernel(const int* __restrict__ qs, const int* __restrict__ qo,
                               const int* __restrict__ qr, const int* __restrict__ qt,
                               const float* __restrict__ b_rt, const float* __restrict__ wp,
                               const float* __restrict__ bp, float* __restrict__ out){
    int w = (blockIdx.x*blockDim.x + threadIdx.x) >> 5;
    int lane = threadIdx.x & 31;
    if (w >= QB) return;
    int s = qs[w], o = qo[w], r = qr[w], t = qt[w];
    int c = lane << 2;
    float4 ra = *(const float4*)&g_RA[r*DIM + c];
    float4 ta = *(const float4*)&g_TA[t*DIM + c];
    float4 bb = *(const float4*)(b_rt + c);
    float q0 = lrelu(ra.x + ta.x + bb.x);
    float q1 = lrelu(ra.y + ta.y + bb.y);
    float q2 = lrelu(ra.z + ta.z + bb.z);
    float q3 = lrelu(ra.w + ta.w + bb.w);
    float4 xs = *(const float4*)&g_x[(size_t)s*DIM + c];
    float4 xo = *(const float4*)&g_x[(size_t)o*DIM + c];
    float4 w1 = *(const float4*)(wp + c);
    float4 w2 = *(const float4*)(wp + 128 + c);
    float4 w3 = *(const float4*)(wp + 256 + c);
    float sum = xs.x*w1.x + xs.y*w1.y + xs.z*w1.z + xs.w*w1.w
              + q0*w2.x + q1*w2.y + q2*w2.z + q3*w2.w
              + xo.x*w3.x + xo.y*w3.y + xo.z*w3.z + xo.w*w3.w;
    #pragma unroll
    for (int d = 16; d; d >>= 1) sum += __shfl_xor_sync(0xffffffffu, sum, d);
    if (lane == 0) out[w] = 1.f / (1.f + expf(-(sum + bp[0])));
}

// ---------------- host ----------------
extern "C" void kernel_launch(void* const* d_in, const int* in_sizes, int n_in,
                              void* d_out, int out_size){
    (void)in_sizes; (void)n_in; (void)out_size;
    const float* x_feat  = (const float*)d_in[0];
    const float* grp     = (const float*)d_in[1];
    const float* rel_emb = (const float*)d_in[2];
    const float* time_e  = (const float*)d_in[3];
    const float* W_node  = (const float*)d_in[4];
    const float* b_node  = (const float*)d_in[5];
    const float* W_rt    = (const float*)d_in[6];
    const float* b_rt    = (const float*)d_in[7];
    const float* W_fc    = (const float*)d_in[8];
    const float* b_fc    = (const float*)d_in[9];
    const float* w_pred  = (const float*)d_in[10];
    const float* b_pred  = (const float*)d_in[11];
    const int* node_ent  = (const int*)d_in[12];
    const int* edge_src  = (const int*)d_in[13];
    const int* edge_dst  = (const int*)d_in[14];
    const int* edge_type = (const int*)d_in[15];
    const int* edge_ts   = (const int*)d_in[16];
    const int* q_s = (const int*)d_in[17];
    const int* q_o = (const int*)d_in[18];
    const int* q_r = (const int*)d_in[19];
    const int* q_t = (const int*)d_in[20];
    float* out = (float*)d_out;

    float *px, *py1, *py3, *pr2t;
    __nv_bfloat16 *pWT;
    void *p_iscr; int *p_tq;
    cudaGetSymbolAddress((void**)&px,    g_x);
    cudaGetSymbolAddress((void**)&py1,   g_Y1);
    cudaGetSymbolAddress((void**)&py3,   g_Y3);
    cudaGetSymbolAddress((void**)&pr2t,  g_R2T);
    cudaGetSymbolAddress((void**)&pWT,   g_WT);
    cudaGetSymbolAddress(&p_iscr, g_iscr);
    p_tq = (int*)p_iscr + 3*NN;

    cudaFuncSetAttribute(hmma_gemm_kernel, cudaFuncAttributeMaxDynamicSharedMemorySize, MMA_SMEM_BYTES);

    // Side streams + fork/join events. Created on the FIRST call (the harness's
    // correctness run, which is NOT captured) and reused in the captured call —
    // the documented fork-join stream-capture pattern. Work is identical on
    // every call; no device memory is allocated.
    static cudaStream_t s2 = 0, s3 = 0;
    static cudaEvent_t eF1 = 0, eF2 = 0, eJ1 = 0, eJ2 = 0;
    if (!s2) {
        cudaStreamCreateWithFlags(&s2, cudaStreamNonBlocking);
        cudaStreamCreateWithFlags(&s3, cudaStreamNonBlocking);
        cudaEventCreateWithFlags(&eF1, cudaEventDisableTiming);
        cudaEventCreateWithFlags(&eF2, cudaEventDisableTiming);
        cudaEventCreateWithFlags(&eJ1, cudaEventDisableTiming);
        cudaEventCreateWithFlags(&eJ2, cudaEventDisableTiming);
    }

    __nv_bfloat16* W1t0 = pWT + 0*16384;  __nv_bfloat16* W1t1 = pWT + 1*16384;
    __nv_bfloat16* W2t0 = pWT + 2*16384;  __nv_bfloat16* W2t1 = pWT + 3*16384;
    __nv_bfloat16* W3t0 = pWT + 4*16384;  __nv_bfloat16* W3t1 = pWT + 5*16384;
    __nv_bfloat16* Wnt0 = pWT + 6*16384;  __nv_bfloat16* Wnt1 = pWT + 7*16384;

    // one memset covers deg / cursor / qmask / tile flags  (default stream)
    cudaMemsetAsync(p_iscr, 0, (3*NN + NT64)*sizeof(int));

    // ---- fork branch 1 (s2): CSR build — independent of all GEMM prep ----
    cudaEventRecord(eF1, 0);
    cudaStreamWaitEvent(s2, eF1, 0);
    hist_kernel<<<(EE+255)/256, 256, 0, s2>>>(edge_dst);
    scan_kernel<<<1, 1024, 0, s2>>>();
    scatter_kernel<<<(EE+255)/256, 256, 0, s2>>>(edge_src, edge_dst, edge_type, edge_ts);
    sortseg_kernel<<<(NN+255)/256, 256, 0, s2>>>();
    cudaEventRecord(eJ1, s2);

    // ---- default stream: weights + small tables + masks ----
    wsplit_all_kernel<<<(4*16384 + 255)/256, 256>>>(W_fc, W_node);
    ra_ta_kernel<<<((NUM_REL+NUM_TS)*128 + 255)/256, 256>>>(rel_emb, time_e, W_rt);
    qmask_kernel<<<1, 256>>>(q_o);

    // ---- fork branch 2 (s3): node-init GEMM (needs wsplit only) ----
    cudaEventRecord(eF2, 0);
    cudaStreamWaitEvent(s3, eF2, 0);
    hmma_gemm_kernel<<<dim3(NT64,1), 256, MMA_SMEM_BYTES, s3>>>(
        x_feat, 0, (const float*)0,
        Wnt0, Wnt1, px, b_node,  (const __nv_bfloat16*)0, (const __nv_bfloat16*)0, (float*)0, (const float*)0,
        DIM, NN, 64, 1, grp, node_ent, (const int*)0);
    cudaEventRecord(eJ2, s3);

    // ---- default: R2T GEMM (runs concurrently with node-init + CSR) ----
    hmma_gemm_kernel<<<dim3((NPAIR+MT-1)/MT,1), 256, MMA_SMEM_BYTES>>>(
        (const float*)0, 1, b_rt,
        W2t0, W2t1, pr2t, b_fc,  (const __nv_bfloat16*)0, (const __nv_bfloat16*)0, (float*)0, (const float*)0,
        DIM, NPAIR, 128, 0, (const float*)0, (const int*)0, (const int*)0);

    // ---- join both branches before the hop loop ----
    cudaStreamWaitEvent(0, eJ1, 0);
    cudaStreamWaitEvent(0, eJ2, 0);

    // 2 full hops + 1 masked final hop; Y1 & Y3 in one launch (gridDim.y = 2)
    for (int hop = 0; hop < 3; hop++){
        const int* tf = (hop == 2) ? p_tq : (const int*)0;
        hmma_gemm_kernel<<<dim3(NT64,2), 256, MMA_SMEM_BYTES>>>(
            px, 0, (const float*)0,
            W1t0, W1t1, py1, (const float*)0,
            W3t0, W3t1, py3, (const float*)0,
            DIM, NN, 128, 0, (const float*)0, (const int*)0, tf);
        aggregate_kernel<<<(NN*32 + 255)/256, 256>>>(hop == 2 ? 1 : 0);
    }

    predict_kernel<<<(QB*32 + 255)/256, 256>>>(q_s, q_o, q_r, q_t, b_rt, w_pred, b_pred, out);
}

// round 17
// speedup vs baseline: 2.4009x; 1.1190x over previous
#include <cuda_runtime.h>
#include <cuda_bf16.h>
#include <math.h>
#include <stdint.h>

// Problem constants (fixed by the dataset instance)
#define NN 20000          // nodes
#define EE 200000         // edges
#define QB 256            // queries
#define NUM_REL 200
#define NUM_TS 365
#define NPAIR (NUM_REL*NUM_TS)   // 73000
#define DIM 128           // 2h
#define MT 64             // GEMM M-tile rows (64 -> 2 CTAs/SM)
#define NT64 ((NN+63)/64)        // 313 row tiles over nodes

// ---------------- scratch (static device globals; no allocation) ----------------
__device__ __align__(128) float g_x[NN*DIM];        // node state
__device__ __align__(128) float g_Y1[NN*DIM];       // x @ W_fc[0:128]
__device__ __align__(128) float g_Y3[NN*DIM];       // x @ W_fc[256:384]
__device__ __align__(128) float g_RA[NUM_REL*DIM];  // rel_emb @ W_rt[0:64]
__device__ __align__(128) float g_TA[NUM_TS*DIM];   // time_emb @ W_rt[64:128]
__device__ __align__(128) float g_R2T[NPAIR*DIM];   // lrelu(RA+TA+b_rt) @ W_fc[128:256] + b_fc

// transposed weight splits, each [128 n-rows][128 k-cols] bf16 (zero padded):
// 0:W1t0 1:W1t1 2:W2t0 3:W2t1 4:W3t0 5:W3t1 6:Wnt0 7:Wnt1
__device__ __align__(128) __nv_bfloat16 g_WT[8*16384];

// contiguous int scratch: [deg NN][cursor NN][qmask NN][tileq NT64]
__device__ int g_iscr[3*NN + NT64];
#define G_DEG (g_iscr)
#define G_CUR (g_iscr + NN)
#define G_QM  (g_iscr + 2*NN)
#define G_TQ  (g_iscr + 3*NN)

__device__ int g_off[NN+1];
__device__ int g_srcS[EE];    // unsorted (atomic scatter order)
__device__ int g_pairS[EE];
__device__ int g_srcT[EE];    // deterministically ordered (rank-scatter output)
__device__ int g_pairT[EE];

__device__ __forceinline__ float lrelu(float v){ return fmaxf(v,0.f) + 0.2f*fminf(v,0.f); }

__device__ __forceinline__ uint32_t smem_u32(const void* p){
    uint32_t a;
    asm("{ .reg .u64 t; cvta.to.shared.u64 t, %1; cvt.u32.u64 %0, t; }" : "=r"(a) : "l"(p));
    return a;
}

// ============================================================================
// HMMA bf16x3 GEMM: C[M, n_out] = A_fp32[M,128] @ ((B0+B1)[n][k])^T
// 64x128 CTA tile -> 104 KB smem -> 2 CTAs/SM. B fill via cp.async (overlaps
// with A fill's LDG+convert). 8 warps in 2(m) x 4(n), warp tile 32x32.
// Fragments via ldmatrix.m8n8.x4 (layout validated: rel_err bit-identical).
// ============================================================================
#define GPAD 136   // bf16 elements per smem row (128 + 8 pad; 272B stride, 16B-aligned)
#define MMA_SMEM_BYTES ((2*MT + 2*128)*GPAD*2)   // A0,A1 (64 rows) + B0,B1 (128 rows) = 104448 B

__device__ __forceinline__ void mma16816(float* c, const uint32_t* a, const uint32_t* b){
    asm volatile(
        "mma.sync.aligned.m16n8k16.row.col.f32.bf16.bf16.f32 "
        "{%0,%1,%2,%3}, {%4,%5,%6,%7}, {%8,%9}, {%0,%1,%2,%3};"
        : "+f"(c[0]), "+f"(c[1]), "+f"(c[2]), "+f"(c[3])
        : "r"(a[0]), "r"(a[1]), "r"(a[2]), "r"(a[3]), "r"(b[0]), "r"(b[1]));
}

__device__ __forceinline__ void ldsm_x4(uint32_t& r0, uint32_t& r1, uint32_t& r2, uint32_t& r3,
                                        uint32_t addr){
    asm volatile("ldmatrix.sync.aligned.m8n8.x4.shared.b16 {%0,%1,%2,%3}, [%4];"
        : "=r"(r0), "=r"(r1), "=r"(r2), "=r"(r3) : "r"(addr));
}

__device__ __forceinline__ void cp_async16(uint32_t smem_dst, const void* gsrc){
    asm volatile("cp.async.ca.shared.global [%0], [%1], 16;"
        :: "r"(smem_dst), "l"(gsrc) : "memory");
}

__device__ __forceinline__ void split_store(float4 v, __nv_bfloat16* d0, __nv_bfloat16* d1){
    __nv_bfloat16 h0=__float2bfloat16(v.x), h1=__float2bfloat16(v.y),
                  h2=__float2bfloat16(v.z), h3=__float2bfloat16(v.w);
    *(__nv_bfloat162*)(d0+0) = __halves2bfloat162(h0,h1);
    *(__nv_bfloat162*)(d0+2) = __halves2bfloat162(h2,h3);
    *(__nv_bfloat162*)(d1+0) = __halves2bfloat162(
        __float2bfloat16(v.x-__bfloat162float(h0)), __float2bfloat16(v.y-__bfloat162float(h1)));
    *(__nv_bfloat162*)(d1+2) = __halves2bfloat162(
        __float2bfloat16(v.z-__bfloat162float(h2)), __float2bfloat16(v.w-__bfloat162float(h3)));
}

__global__ __launch_bounds__(256, 2) void hmma_gemm_kernel(
    const float* __restrict__ A, int amode, const float* __restrict__ b_rt,
    const __nv_bfloat16* __restrict__ B0a, const __nv_bfloat16* __restrict__ B1a,
    float* __restrict__ Ca, const float* __restrict__ biasA,
    const __nv_bfloat16* __restrict__ B0b, const __nv_bfloat16* __restrict__ B1b,
    float* __restrict__ Cb, const float* __restrict__ biasB,
    int ldc, int M, int n_out, int act,
    const float* __restrict__ grp, const int* __restrict__ ent,
    const int* __restrict__ tflags)
{
    const int which = blockIdx.y;
    if (tflags && which == 1 && tflags[blockIdx.x] == 0) return;
    const __nv_bfloat16* Bt0 = which ? B0b : B0a;
    const __nv_bfloat16* Bt1 = which ? B1b : B1a;
    float* C = which ? Cb : Ca;
    const float* bias = which ? biasB : biasA;

    extern __shared__ __align__(16) char smem[];
    __nv_bfloat16* sA0 = (__nv_bfloat16*)smem;              // MT x GPAD
    __nv_bfloat16* sA1 = sA0 + MT*GPAD;                      // MT x GPAD

    const int tid = threadIdx.x;
    const int wid = tid >> 5, lane = tid & 31;
    const int bm = blockIdx.x * MT;

    const uint32_t sbase = smem_u32(smem);
    const uint32_t uA0 = sbase;
    const uint32_t uA1 = sbase + MT*GPAD*2;
    const uint32_t uB0 = sbase + 2*MT*GPAD*2;
    const uint32_t uB1 = uB0 + 128*GPAD*2;

    // ---- B tiles via cp.async (issued FIRST; overlaps A's LDG+convert) ----
    #pragma unroll
    for (int t = 0; t < 8; t++) {
        int idx = tid + t*256;               // 2048 16B slots
        int row = idx >> 4, c8 = (idx & 15) << 3;
        uint32_t so = (uint32_t)(row*GPAD + c8) * 2u;
        cp_async16(uB0 + so, Bt0 + (size_t)row*128 + c8);
        cp_async16(uB1 + so, Bt1 + (size_t)row*128 + c8);
    }
    asm volatile("cp.async.commit_group;" ::: "memory");

    // ---- fill A (fp32 -> bf16 hi/lo split); amode 1 = RELT rows on the fly ----
    #pragma unroll
    for (int t = 0; t < 8; t++) {
        int idx = tid + t*256;               // MT*32 = 2048 float4 slots
        int row = idx >> 5, c4 = (idx & 31) << 2;
        float4 v = make_float4(0.f,0.f,0.f,0.f);
        int gr = bm + row;
        if (gr < M) {
            if (amode == 0) {
                v = *(const float4*)(A + (size_t)gr*128 + c4);
            } else {
                int r_ = gr / NUM_TS, t_ = gr - r_*NUM_TS;
                float4 ra = *(const float4*)&g_RA[r_*DIM + c4];
                float4 ta = *(const float4*)&g_TA[t_*DIM + c4];
                float4 bb = *(const float4*)(b_rt + c4);
                v.x = lrelu(ra.x + ta.x + bb.x);
                v.y = lrelu(ra.y + ta.y + bb.y);
                v.z = lrelu(ra.z + ta.z + bb.z);
                v.w = lrelu(ra.w + ta.w + bb.w);
            }
        }
        split_store(v, sA0 + row*GPAD + c4, sA1 + row*GPAD + c4);
    }
    // ---- fused grp gather (node-init only): x[:,64:128] = grp[ent] ----
    if (ent) {
        #pragma unroll
        for (int t = 0; t < 4; t++) {
            int idx = tid + t*256;           // MT*16 = 1024 float4
            int row = idx >> 4, c4 = (idx & 15) << 2;
            int gr = bm + row;
            if (gr < M)
                *(float4*)(Ca + (size_t)gr*ldc + 64 + c4) =
                    *(const float4*)(grp + (size_t)ent[gr]*64 + c4);
        }
    }
    asm volatile("cp.async.wait_group 0;" ::: "memory");
    __syncthreads();

    const int warp_m = wid & 1;              // 0..1 -> m offset 32*warp_m
    const int warp_n = wid >> 1;             // 0..3 -> n offset 32*warp_n
    const int gid = lane >> 2;               // 0..7
    const int q2  = (lane & 3) << 1;         // 0,2,4,6

    // ldmatrix lane-address offsets (bf16 elements) — validated layout
    const int g8 = lane >> 3, ri = lane & 7;
    const uint32_t aoff = (uint32_t)(((g8 & 1)*8 + ri)*GPAD + (g8 >> 1)*8);
    const uint32_t boff = (uint32_t)(((g8 >> 1)*8 + ri)*GPAD + (g8 & 1)*8);
    const uint32_t aAddr0 = (uint32_t)((warp_m*32)*GPAD) + aoff;        // i=0
    const uint32_t aAddr1 = aAddr0 + 16*GPAD;                            // i=1
    uint32_t bAddr[2];
    #pragma unroll
    for (int jj = 0; jj < 2; jj++)
        bAddr[jj] = (uint32_t)((warp_n*32 + jj*16)*GPAD) + boff;

    float acc[2][4][4];
    #pragma unroll
    for (int i = 0; i < 2; i++)
        #pragma unroll
        for (int j = 0; j < 4; j++)
            #pragma unroll
            for (int q = 0; q < 4; q++) acc[i][j][q] = 0.f;

    #pragma unroll 1
    for (int p = 0; p < 3; p++) {
        const uint32_t Ab = (p == 2) ? uA1 : uA0;
        const uint32_t Bb = (p == 1) ? uB1 : uB0;
        #pragma unroll
        for (int ks = 0; ks < 8; ks++) {
            const uint32_t koff = (uint32_t)ks * 32u;   // 16 bf16 = 32 bytes
            uint32_t a[2][4];
            ldsm_x4(a[0][0], a[0][1], a[0][2], a[0][3], Ab + aAddr0*2 + koff);
            ldsm_x4(a[1][0], a[1][1], a[1][2], a[1][3], Ab + aAddr1*2 + koff);
            uint32_t b[4][2];
            #pragma unroll
            for (int jj = 0; jj < 2; jj++)
                ldsm_x4(b[2*jj][0], b[2*jj][1], b[2*jj+1][0], b[2*jj+1][1],
                        Bb + bAddr[jj]*2 + koff);
            #pragma unroll
            for (int i = 0; i < 2; i++)
                #pragma unroll
                for (int j = 0; j < 4; j++)
                    mma16816(acc[i][j], a[i], b[j]);
        }
    }

    // ---- epilogue ----
    #pragma unroll
    for (int i = 0; i < 2; i++) {
        int row0 = bm + warp_m*32 + i*16 + gid;
        #pragma unroll
        for (int j = 0; j < 4; j++) {
            int col = warp_n*32 + j*8 + q2;
            if (col >= n_out) continue;
            float bx = 0.f, by = 0.f;
            if (bias) { float2 bb = *(const float2*)(bias + col); bx = bb.x; by = bb.y; }
            if (row0 < M) {
                float2 o = make_float2(acc[i][j][0] + bx, acc[i][j][1] + by);
                if (act) { o.x = lrelu(o.x); o.y = lrelu(o.y); }
                *(float2*)(C + (size_t)row0*ldc + col) = o;
            }
            if (row0 + 8 < M) {
                float2 o = make_float2(acc[i][j][2] + bx, acc[i][j][3] + by);
                if (act) { o.x = lrelu(o.x); o.y = lrelu(o.y); }
                *(float2*)(C + (size_t)(row0+8)*ldc + col) = o;
            }
        }
    }
}

// ---------------- fused small GEMM: RA (M=200) then TA (M=365) ----------------
__global__ void ra_ta_kernel(const float* __restrict__ rel_emb, const float* __restrict__ time_e,
                             const float* __restrict__ W_rt){
    int idx = blockIdx.x*blockDim.x + threadIdx.x;
    int total = (NUM_REL + NUM_TS) * 128;
    if (idx >= total) return;
    int row = idx >> 7, col = idx & 127;
    const float* a; const float* B; float* C;
    if (row < NUM_REL) { a = rel_emb + row*64;           B = W_rt;          C = &g_RA[row*DIM + col]; }
    else { int r2 = row - NUM_REL; a = time_e + r2*64;   B = W_rt + 64*128; C = &g_TA[r2*DIM + col]; }
    float s = 0.f;
    #pragma unroll
    for (int k = 0; k < 64; k++) s = fmaf(__ldg(a + k), __ldg(B + k*128 + col), s);
    *C = s;
}

// ---------------- all 4 weight transposes + splits in one launch ----------------
__global__ void wsplit_all_kernel(const float* __restrict__ W_fc, const float* __restrict__ W_node){
    int idx = blockIdx.x*blockDim.x + threadIdx.x;
    if (idx >= 4*16384) return;
    int which = idx >> 14, sub = idx & 16383;
    int n = sub >> 7, k = sub & 127;
    float v;
    if (which < 3) v = W_fc[(size_t)which*128*128 + k*128 + n];
    else           v = (n < 64) ? W_node[k*64 + n] : 0.f;
    __nv_bfloat16 h = __float2bfloat16(v);
    g_WT[(size_t)which*2*16384 + sub]         = h;
    g_WT[(size_t)which*2*16384 + 16384 + sub] = __float2bfloat16(v - __bfloat162float(h));
}

// ---------------- CSR build ----------------
__global__ void hist_kernel(const int* __restrict__ dst){
    int e = blockIdx.x*blockDim.x + threadIdx.x;
    if (e < EE) atomicAdd(&G_DEG[dst[e]], 1);
}

__global__ void scan_kernel(){
    __shared__ int warp_sums[32];
    __shared__ int s_carry;
    int tid = threadIdx.x;
    int lane = tid & 31, wid = tid >> 5;
    if (tid == 0) s_carry = 0;
    __syncthreads();
    for (int base = 0; base < NN; base += 1024){
        int i = base + tid;
        int v = (i < NN) ? G_DEG[i] : 0;
        int x = v;
        #pragma unroll
        for (int d = 1; d < 32; d <<= 1){
            int y = __shfl_up_sync(0xffffffffu, x, d);
            if (lane >= d) x += y;
        }
        if (lane == 31) warp_sums[wid] = x;
        __syncthreads();
        if (tid < 32){
            int w = warp_sums[tid];
            #pragma unroll
            for (int d = 1; d < 32; d <<= 1){
                int y = __shfl_up_sync(0xffffffffu, w, d);
                if (tid >= d) w += y;
            }
            warp_sums[tid] = w;
        }
        __syncthreads();
        int prefix = s_carry + (wid ? warp_sums[wid-1] : 0);
        if (i < NN) g_off[i] = x + prefix - v;   // exclusive
        __syncthreads();
        if (tid == 0) s_carry += warp_sums[31];
        __syncthreads();
    }
    if (threadIdx.x == 0) g_off[NN] = s_carry;
}

__global__ void scatter_kernel(const int* __restrict__ src, const int* __restrict__ dst,
                               const int* __restrict__ rel, const int* __restrict__ ts){
    int e = blockIdx.x*blockDim.x + threadIdx.x;
    if (e >= EE) return;
    int d = dst[e];
    int pos = g_off[d] + atomicAdd(&G_CUR[d], 1);
    g_srcS[pos]  = src[e];
    g_pairS[pos] = rel[e]*NUM_TS + ts[e];
}

// warp-per-node deterministic rank-scatter: out[beg+rank] = in[i] where
// rank = #{j : key_j < key_i or (key_j == key_i and j < i)}.
// Inner-loop loads are warp-uniform (broadcast). Output order identical to a
// stable sort by (src, pair) — fully deterministic regardless of scatter order.
__global__ __launch_bounds__(256) void rank_scatter_kernel(){
    int w = (blockIdx.x*blockDim.x + threadIdx.x) >> 5;
    int lane = threadIdx.x & 31;
    if (w >= NN) return;
    int beg = g_off[w], end = g_off[w+1];
    int deg = end - beg;
    for (int i = lane; i < deg; i += 32){
        int si = g_srcS[beg+i], pi = g_pairS[beg+i];
        long long ki = ((long long)si << 17) | pi;
        int rank = 0;
        for (int j = 0; j < deg; j++){
            long long kj = ((long long)g_srcS[beg+j] << 17) | g_pairS[beg+j];
            rank += (kj < ki) || (kj == ki && j < i);
        }
        g_srcT[beg+rank]  = si;
        g_pairT[beg+rank] = pi;
    }
}

__global__ void qmask_kernel(const int* __restrict__ qo){
    int b = threadIdx.x;
    if (b < QB) {
        int n = qo[b];
        G_QM[n] = 1;
        G_TQ[n >> 6] = 1;    // 64-row GEMM tiles
    }
}

// ---------------- fused aggregate: x[n] += mean_e lrelu(Y1[src]+R2T[pair]+Y3[n]) ----------------
__global__ __launch_bounds__(256) void aggregate_kernel(int masked){
    int w = (blockIdx.x*blockDim.x + threadIdx.x) >> 5;
    int lane = threadIdx.x & 31;
    if (w >= NN) return;
    if (masked && G_QM[w] == 0) return;
    int beg = g_off[w], end = g_off[w+1];
    if (beg == end) return;
    int c = lane << 2;
    float4 y3 = *(const float4*)&g_Y3[(size_t)w*DIM + c];
    float4 acc = make_float4(0.f,0.f,0.f,0.f);
    int i = beg;
    for (; i + 1 < end; i += 2){
        int s0 = g_srcT[i],   p0 = g_pairT[i];
        int s1 = g_srcT[i+1], p1 = g_pairT[i+1];
        float4 a0 = *(const float4*)&g_Y1[(size_t)s0*DIM + c];
        float4 b0 = *(const float4*)&g_R2T[(size_t)p0*DIM + c];
        float4 a1 = *(const float4*)&g_Y1[(size_t)s1*DIM + c];
        float4 b1 = *(const float4*)&g_R2T[(size_t)p1*DIM + c];
        acc.x += lrelu(a0.x + b0.x + y3.x);
        acc.y += lrelu(a0.y + b0.y + y3.y);
        acc.z += lrelu(a0.z + b0.z + y3.z);
        acc.w += lrelu(a0.w + b0.w + y3.w);
        acc.x += lrelu(a1.x + b1.x + y3.x);
        acc.y += lrelu(a1.y + b1.y + y3.y);
        acc.z += lrelu(a1.z + b1.z + y3.z);
        acc.w += lrelu(a1.w + b1.w + y3.w);
    }
    if (i < end){
        int s0 = g_srcT[i], p0 = g_pairT[i];
        float4 a0 = *(const float4*)&g_Y1[(size_t)s0*DIM + c];
        float4 b0 = *(const float4*)&g_R2T[(size_t)p0*DIM + c];
        acc.x += lrelu(a0.x + b0.x + y3.x);
        acc.y += lrelu(a0.y + b0.y + y3.y);
        acc.z += lrelu(a0.z + b0.z + y3.z);
        acc.w += lrelu(a0.w + b0.w + y3.w);
    }
    float inv = 1.f / (float)(end - beg);
    float4* xp = (float4*)&g_x[(size_t)w*DIM + c];
    float4 xv = *xp;
    xv.x += acc.x*inv; xv.y += acc.y*inv; xv.z += acc.z*inv; xv.w += acc.w*inv;
    *xp = xv;
}

// ---------------- prediction ----------------
__global__ void predict_kernel(const int* __restrict__ qs, const int* __restrict__ qo,
                               const int* __restrict__ qr, const int* __restrict__ qt,
                               const float* __restrict__ b_rt, const float* __restrict__ wp,
                               const float* __restrict__ bp, float* __restrict__ out){
    int w = (blockIdx.x*blockDim.x + threadIdx.x) >> 5;
    int lane = threadIdx.x & 31;
    if (w >= QB) return;
    int s = qs[w], o = qo[w], r = qr[w], t = qt[w];
    int c = lane << 2;
    float4 ra = *(const float4*)&g_RA[r*DIM + c];
    float4 ta = *(const float4*)&g_TA[t*DIM + c];
    float4 bb = *(const float4*)(b_rt + c);
    float q0 = lrelu(ra.x + ta.x + bb.x);
    float q1 = lrelu(ra.y + ta.y + bb.y);
    float q2 = lrelu(ra.z + ta.z + bb.z);
    float q3 = lrelu(ra.w + ta.w + bb.w);
    float4 xs = *(const float4*)&g_x[(size_t)s*DIM + c];
    float4 xo = *(const float4*)&g_x[(size_t)o*DIM + c];
    float4 w1 = *(const float4*)(wp + c);
    float4 w2 = *(const float4*)(wp + 128 + c);
    float4 w3 = *(const float4*)(wp + 256 + c);
    float sum = xs.x*w1.x + xs.y*w1.y + xs.z*w1.z + xs.w*w1.w
              + q0*w2.x + q1*w2.y + q2*w2.z + q3*w2.w
              + xo.x*w3.x + xo.y*w3.y + xo.z*w3.z + xo.w*w3.w;
    #pragma unroll
    for (int d = 16; d; d >>= 1) sum += __shfl_xor_sync(0xffffffffu, sum, d);
    if (lane == 0) out[w] = 1.f / (1.f + expf(-(sum + bp[0])));
}

// ---------------- host ----------------
extern "C" void kernel_launch(void* const* d_in, const int* in_sizes, int n_in,
                              void* d_out, int out_size){
    (void)in_sizes; (void)n_in; (void)out_size;
    const float* x_feat  = (const float*)d_in[0];
    const float* grp     = (const float*)d_in[1];
    const float* rel_emb = (const float*)d_in[2];
    const float* time_e  = (const float*)d_in[3];
    const float* W_node  = (const float*)d_in[4];
    const float* b_node  = (const float*)d_in[5];
    const float* W_rt    = (const float*)d_in[6];
    const float* b_rt    = (const float*)d_in[7];
    const float* W_fc    = (const float*)d_in[8];
    const float* b_fc    = (const float*)d_in[9];
    const float* w_pred  = (const float*)d_in[10];
    const float* b_pred  = (const float*)d_in[11];
    const int* node_ent  = (const int*)d_in[12];
    const int* edge_src  = (const int*)d_in[13];
    const int* edge_dst  = (const int*)d_in[14];
    const int* edge_type = (const int*)d_in[15];
    const int* edge_ts   = (const int*)d_in[16];
    const int* q_s = (const int*)d_in[17];
    const int* q_o = (const int*)d_in[18];
    const int* q_r = (const int*)d_in[19];
    const int* q_t = (const int*)d_in[20];
    float* out = (float*)d_out;

    float *px, *py1, *py3, *pr2t;
    __nv_bfloat16 *pWT;
    void *p_iscr; int *p_tq;
    cudaGetSymbolAddress((void**)&px,    g_x);
    cudaGetSymbolAddress((void**)&py1,   g_Y1);
    cudaGetSymbolAddress((void**)&py3,   g_Y3);
    cudaGetSymbolAddress((void**)&pr2t,  g_R2T);
    cudaGetSymbolAddress((void**)&pWT,   g_WT);
    cudaGetSymbolAddress(&p_iscr, g_iscr);
    p_tq = (int*)p_iscr + 3*NN;

    cudaFuncSetAttribute(hmma_gemm_kernel, cudaFuncAttributeMaxDynamicSharedMemorySize, MMA_SMEM_BYTES);

    // Side streams + fork/join events. Created on the FIRST call (the harness's
    // correctness run, which is NOT captured) and reused in the captured call —
    // the documented fork-join stream-capture pattern. Work is identical on
    // every call; no device memory is allocated.
    static cudaStream_t s2 = 0, s3 = 0;
    static cudaEvent_t eF1 = 0, eF2 = 0, eJ1 = 0, eJ2 = 0;
    if (!s2) {
        cudaStreamCreateWithFlags(&s2, cudaStreamNonBlocking);
        cudaStreamCreateWithFlags(&s3, cudaStreamNonBlocking);
        cudaEventCreateWithFlags(&eF1, cudaEventDisableTiming);
        cudaEventCreateWithFlags(&eF2, cudaEventDisableTiming);
        cudaEventCreateWithFlags(&eJ1, cudaEventDisableTiming);
        cudaEventCreateWithFlags(&eJ2, cudaEventDisableTiming);
    }

    __nv_bfloat16* W1t0 = pWT + 0*16384;  __nv_bfloat16* W1t1 = pWT + 1*16384;
    __nv_bfloat16* W2t0 = pWT + 2*16384;  __nv_bfloat16* W2t1 = pWT + 3*16384;
    __nv_bfloat16* W3t0 = pWT + 4*16384;  __nv_bfloat16* W3t1 = pWT + 5*16384;
    __nv_bfloat16* Wnt0 = pWT + 6*16384;  __nv_bfloat16* Wnt1 = pWT + 7*16384;

    // one memset covers deg / cursor / qmask / tile flags  (default stream)
    cudaMemsetAsync(p_iscr, 0, (3*NN + NT64)*sizeof(int));

    // ---- fork branch 1 (s2): CSR build — independent of all GEMM prep ----
    cudaEventRecord(eF1, 0);
    cudaStreamWaitEvent(s2, eF1, 0);
    hist_kernel<<<(EE+255)/256, 256, 0, s2>>>(edge_dst);
    scan_kernel<<<1, 1024, 0, s2>>>();
    scatter_kernel<<<(EE+255)/256, 256, 0, s2>>>(edge_src, edge_dst, edge_type, edge_ts);
    rank_scatter_kernel<<<(NN*32 + 255)/256, 256, 0, s2>>>();
    cudaEventRecord(eJ1, s2);

    // ---- default stream: weights + small tables + masks ----
    wsplit_all_kernel<<<(4*16384 + 255)/256, 256>>>(W_fc, W_node);
    ra_ta_kernel<<<((NUM_REL+NUM_TS)*128 + 255)/256, 256>>>(rel_emb, time_e, W_rt);
    qmask_kernel<<<1, 256>>>(q_o);

    // ---- fork branch 2 (s3): node-init GEMM (needs wsplit only) ----
    cudaEventRecord(eF2, 0);
    cudaStreamWaitEvent(s3, eF2, 0);
    hmma_gemm_kernel<<<dim3(NT64,1), 256, MMA_SMEM_BYTES, s3>>>(
        x_feat, 0, (const float*)0,
        Wnt0, Wnt1, px, b_node,  (const __nv_bfloat16*)0, (const __nv_bfloat16*)0, (float*)0, (const float*)0,
        DIM, NN, 64, 1, grp, node_ent, (const int*)0);
    cudaEventRecord(eJ2, s3);

    // ---- default: R2T GEMM (runs concurrently with node-init + CSR) ----
    hmma_gemm_kernel<<<dim3((NPAIR+MT-1)/MT,1), 256, MMA_SMEM_BYTES>>>(
        (const float*)0, 1, b_rt,
        W2t0, W2t1, pr2t, b_fc,  (const __nv_bfloat16*)0, (const __nv_bfloat16*)0, (float*)0, (const float*)0,
        DIM, NPAIR, 128, 0, (const float*)0, (const int*)0, (const int*)0);

    // ---- join both branches before the hop loop ----
    cudaStreamWaitEvent(0, eJ1, 0);
    cudaStreamWaitEvent(0, eJ2, 0);

    // 2 full hops + 1 masked final hop; Y1 & Y3 in one launch (gridDim.y = 2)
    for (int hop = 0; hop < 3; hop++){
        const int* tf = (hop == 2) ? p_tq : (const int*)0;
        hmma_gemm_kernel<<<dim3(NT64,2), 256, MMA_SMEM_BYTES>>>(
            px, 0, (const float*)0,
            W1t0, W1t1, py1, (const float*)0,
            W3t0, W3t1, py3, (const float*)0,
            DIM, NN, 128, 0, (const float*)0, (const int*)0, tf);
        aggregate_kernel<<<(NN*32 + 255)/256, 256>>>(hop == 2 ? 1 : 0);
    }

    predict_kernel<<<(QB*32 + 255)/256, 256>>>(q_s, q_o, q_r, q_t, b_rt, w_pred, b_pred, out);
}